// round 6
// baseline (speedup 1.0000x reference)
#include <cuda_runtime.h>
#include <cuda_bf16.h>
#include <mma.h>
using namespace nvcuda;

#define DIM 128
#define MAX_NODES 65536
#define TILE_E 128

__device__ float g_Q[MAX_NODES * 256];
__device__ int g_idx64;

// ---------------------------------------------------------------------------
__global__ void detect_idx_kernel(const unsigned int* __restrict__ w) {
    __shared__ int s_any;
    if (threadIdx.x == 0) s_any = 0;
    __syncthreads();
    int found = 0;
    for (int i = threadIdx.x; i < 4096; i += blockDim.x)
        if (w[2 * i + 1] != 0u) found = 1;
    if (found) atomicOr(&s_any, 1);
    __syncthreads();
    if (threadIdx.x == 0) g_idx64 = (s_any == 0) ? 1 : 0;
}

// ---------------------------------------------------------------------------
// bf16 split helper: v = hi + lo with ~16-bit combined mantissa
__device__ __forceinline__ void split2(float v0, float v1, unsigned& h, unsigned& l) {
    __nv_bfloat162 hh = __floats2bfloat162_rn(v0, v1);
    float2 hf = __bfloat1622float2(hh);
    __nv_bfloat162 ll = __floats2bfloat162_rn(v0 - hf.x, v1 - hf.y);
    h = *(unsigned*)&hh;
    l = *(unsigned*)&ll;
}

typedef wmma::fragment<wmma::matrix_a, 16, 16, 16, __nv_bfloat16, wmma::row_major> FragA;
typedef wmma::fragment<wmma::matrix_b, 16, 16, 16, __nv_bfloat16, wmma::row_major> FragB;
typedef wmma::fragment<wmma::accumulator, 16, 16, 16, float> FragC;

// ---------------------------------------------------------------------------
// Precompute: Q[node][0:256] = (nf[node]-centroid[g]) @ [W1b | W1c]
// Dense GEMM M=128/CTA, N=256, K=128, bf16-split (hh+hl+lh), fp32 acc.
// A stride 136 (conflict-free), W stride 264. Acc stored straight to g_Q.
// ---------------------------------------------------------------------------
#define PRE_SMEM ((128 * 264 * 2 + 128 * 136 * 2) * 2)

__global__ __launch_bounds__(128)
void precompute_kernel(const float* __restrict__ nf, const float* __restrict__ centroid,
                       const float* __restrict__ W1, int n_nodes, int npg) {
    extern __shared__ char sm[];
    __nv_bfloat16* sW_hi = (__nv_bfloat16*)sm;            // [128][264]
    __nv_bfloat16* sW_lo = sW_hi + 128 * 264;
    __nv_bfloat16* sA_hi = sW_lo + 128 * 264;             // [128][136]
    __nv_bfloat16* sA_lo = sA_hi + 128 * 136;

    const int t = threadIdx.x;
    const int base = blockIdx.x * 128;

    for (int i = t; i < 128 * 256; i += 128) {
        int k = i >> 8, n = i & 255;
        float w = (n < 128) ? W1[DIM * DIM + k * DIM + n]
                            : W1[2 * DIM * DIM + k * DIM + (n - 128)];
        __nv_bfloat16 hi = __float2bfloat16(w);
        __nv_bfloat16 lo = __float2bfloat16(w - __bfloat162float(hi));
        sW_hi[k * 264 + n] = hi;
        sW_lo[k * 264 + n] = lo;
    }
    __syncthreads();

    if (base + 128 > n_nodes) {   // scalar fallback for a partial tile
        for (int node = base; node < n_nodes; node++) {
            const float* row = nf + (size_t)node * DIM;
            const float* cen = centroid + (size_t)(node / npg) * DIM;
            for (int c = t; c < 256; c += 128) {
                const float* wc = (c < 128) ? W1 + DIM * DIM + c
                                            : W1 + 2 * DIM * DIM + (c - 128);
                float acc = 0.f;
                for (int k = 0; k < DIM; k++) acc += (row[k] - cen[k]) * wc[k * DIM];
                g_Q[(size_t)node * 256 + c] = acc;
            }
        }
        return;
    }

    // residual row t -> sA hi/lo (thread-private row)
    {
        int node = base + t;
        const float4* pn = (const float4*)(nf + (size_t)node * DIM);
        const float4* pc = (const float4*)(centroid + (size_t)(node / npg) * DIM);
        unsigned* rh = (unsigned*)(sA_hi + t * 136);
        unsigned* rl = (unsigned*)(sA_lo + t * 136);
#pragma unroll
        for (int g = 0; g < 32; g++) {
            float4 a = pn[g], c = pc[g];
            unsigned h0, l0, h1, l1;
            split2(a.x - c.x, a.y - c.y, h0, l0);
            split2(a.z - c.z, a.w - c.w, h1, l1);
            rh[2 * g] = h0; rh[2 * g + 1] = h1;
            rl[2 * g] = l0; rl[2 * g + 1] = l1;
        }
    }
    __syncwarp();

    const int w = t >> 5;
    for (int chunk = 0; chunk < 4; chunk++) {
        FragC acc[2][4];
#pragma unroll
        for (int m = 0; m < 2; m++)
#pragma unroll
            for (int n = 0; n < 4; n++) wmma::fill_fragment(acc[m][n], 0.f);

#pragma unroll
        for (int k = 0; k < 8; k++) {
            FragA a_hi[2], a_lo[2];
#pragma unroll
            for (int m = 0; m < 2; m++) {
                const __nv_bfloat16* ap = sA_hi + (w * 32 + m * 16) * 136 + k * 16;
                wmma::load_matrix_sync(a_hi[m], ap, 136);
                wmma::load_matrix_sync(a_lo[m], ap + 128 * 136, 136);
            }
#pragma unroll
            for (int n = 0; n < 4; n++) {
                FragB b_hi, b_lo;
                const __nv_bfloat16* bp = sW_hi + (k * 16) * 264 + chunk * 64 + n * 16;
                wmma::load_matrix_sync(b_hi, bp, 264);
                wmma::load_matrix_sync(b_lo, bp + 128 * 264, 264);
#pragma unroll
                for (int m = 0; m < 2; m++) {
                    wmma::mma_sync(acc[m][n], a_hi[m], b_hi, acc[m][n]);
                    wmma::mma_sync(acc[m][n], a_hi[m], b_lo, acc[m][n]);
                    wmma::mma_sync(acc[m][n], a_lo[m], b_hi, acc[m][n]);
                }
            }
        }
#pragma unroll
        for (int m = 0; m < 2; m++)
#pragma unroll
            for (int n = 0; n < 4; n++)
                wmma::store_matrix_sync(
                    g_Q + (size_t)(base + w * 32 + m * 16) * 256 + chunk * 64 + n * 16,
                    acc[m][n], 256, wmma::mem_row_major);
    }
}

// ---------------------------------------------------------------------------
// Edge kernel: 128 threads / 4 warps; per 128-edge tile:
//   A[e][d] = |nf[dst]-nf[src]| (bf16 hi/lo, stride 136)
//   H = A @ W1a (bf16-split), acc fp32 via sOut (stride 132)
//   out[e] = relu(H + Q[dst] + Q[src][128:] + b1) . W2 + b2
// All smem rows warp-private -> no __syncthreads in the loop; warps drift,
// overlapping L2 gathers with tensor MMA.
// ---------------------------------------------------------------------------
#define EDGE_SMEM (128 * 136 * 2 * 2 /*W*/ + 128 * 136 * 2 * 2 /*A*/ \
                   + 128 * 132 * 4 /*Out*/ + 128 * 4 * 2 /*b1,W2*/)

__global__ __launch_bounds__(128, 1)
void edge_kernel(const float* __restrict__ nf, const void* __restrict__ ei,
                 const float* __restrict__ W1, const float* __restrict__ b1,
                 const float* __restrict__ W2, const float* __restrict__ b2,
                 float* __restrict__ out, int E) {
    extern __shared__ char sm[];
    __nv_bfloat16* sW_hi = (__nv_bfloat16*)sm;            // [128 k][136]
    __nv_bfloat16* sW_lo = sW_hi + 128 * 136;
    __nv_bfloat16* sA_hi = sW_lo + 128 * 136;             // [128 e][136]
    __nv_bfloat16* sA_lo = sA_hi + 128 * 136;
    float* sOut = (float*)(sA_lo + 128 * 136);            // [128 e][132]
    float* sB1  = sOut + 128 * 132;
    float* sW2  = sB1 + 128;

    const int t = threadIdx.x;
    const int w = t >> 5;

    // stage W1a (rows 0..127 of W1: the |.| block) as bf16 hi/lo
    for (int i = t; i < DIM * DIM; i += 128) {
        float v = W1[i];   // [k][n]
        __nv_bfloat16 hi = __float2bfloat16(v);
        __nv_bfloat16 lo = __float2bfloat16(v - __bfloat162float(hi));
        int k = i >> 7, n = i & 127;
        sW_hi[k * 136 + n] = hi;
        sW_lo[k * 136 + n] = lo;
    }
    if (t < DIM) { sB1[t] = b1[t]; sW2[t] = W2[t]; }
    __syncthreads();

    const float bias2 = b2[0];
    const int mode64 = g_idx64;
    const long long* ei64 = (const long long*)ei;
    const int* ei32 = (const int*)ei;

    const int tiles = (E + TILE_E - 1) / TILE_E;
    for (int tile = blockIdx.x; tile < tiles; tile += gridDim.x) {
        const int eid = tile * TILE_E + t;
        int src = 0, dst = 0;
        if (eid < E) {
            if (mode64) { src = (int)ei64[eid]; dst = (int)ei64[E + eid]; }
            else        { src = ei32[eid];      dst = ei32[E + eid]; }
        }

        // gather |nf[dst]-nf[src]| into own A row (hi/lo)
        {
            const float4* pi = (const float4*)(nf + (size_t)dst * DIM);
            const float4* pj = (const float4*)(nf + (size_t)src * DIM);
            unsigned* rh = (unsigned*)(sA_hi + t * 136);
            unsigned* rl = (unsigned*)(sA_lo + t * 136);
#pragma unroll
            for (int g = 0; g < 32; g++) {
                float4 a = pi[g], b = pj[g];
                unsigned h0, l0, h1, l1;
                split2(fabsf(a.x - b.x), fabsf(a.y - b.y), h0, l0);
                split2(fabsf(a.z - b.z), fabsf(a.w - b.w), h1, l1);
                rh[2 * g] = h0; rh[2 * g + 1] = h1;
                rl[2 * g] = l0; rl[2 * g + 1] = l1;
            }
        }
        __syncwarp();

        // H = A @ W1a, two N-halves of 64, warp-private m rows (w*32..w*32+32)
#pragma unroll 1
        for (int nh = 0; nh < 2; nh++) {
            FragC acc[2][4];
#pragma unroll
            for (int m = 0; m < 2; m++)
#pragma unroll
                for (int n = 0; n < 4; n++) wmma::fill_fragment(acc[m][n], 0.f);

#pragma unroll
            for (int k = 0; k < 8; k++) {
                FragA a_hi[2], a_lo[2];
#pragma unroll
                for (int m = 0; m < 2; m++) {
                    const __nv_bfloat16* ap = sA_hi + (w * 32 + m * 16) * 136 + k * 16;
                    wmma::load_matrix_sync(a_hi[m], ap, 136);
                    wmma::load_matrix_sync(a_lo[m], ap + 128 * 136, 136);
                }
#pragma unroll
                for (int n = 0; n < 4; n++) {
                    FragB b_hi, b_lo;
                    const __nv_bfloat16* bp = sW_hi + (k * 16) * 136 + nh * 64 + n * 16;
                    wmma::load_matrix_sync(b_hi, bp, 136);
                    wmma::load_matrix_sync(b_lo, bp + 128 * 136, 136);
#pragma unroll
                    for (int m = 0; m < 2; m++) {
                        wmma::mma_sync(acc[m][n], a_hi[m], b_hi, acc[m][n]);
                        wmma::mma_sync(acc[m][n], a_hi[m], b_lo, acc[m][n]);
                        wmma::mma_sync(acc[m][n], a_lo[m], b_hi, acc[m][n]);
                    }
                }
            }
#pragma unroll
            for (int m = 0; m < 2; m++)
#pragma unroll
                for (int n = 0; n < 4; n++)
                    wmma::store_matrix_sync(
                        sOut + (w * 32 + m * 16) * 132 + nh * 64 + n * 16,
                        acc[m][n], 132, wmma::mem_row_major);
        }
        __syncwarp();

        // epilogue: own row of sOut + Q gathers, relu, dot W2
        {
            const float4* o4 = (const float4*)(sOut + t * 132);
            const float4* qd = (const float4*)(g_Q + (size_t)dst * 256);
            const float4* qs = (const float4*)(g_Q + (size_t)src * 256 + 128);
            const float4* b4 = (const float4*)sB1;
            const float4* w4 = (const float4*)sW2;
            float s = 0.f;
#pragma unroll 8
            for (int q = 0; q < 32; q++) {
                float4 o = o4[q], a = qd[q], b = qs[q], bb = b4[q], ww = w4[q];
                s += fmaxf(o.x + a.x + b.x + bb.x, 0.f) * ww.x
                   + fmaxf(o.y + a.y + b.y + bb.y, 0.f) * ww.y
                   + fmaxf(o.z + a.z + b.z + bb.z, 0.f) * ww.z
                   + fmaxf(o.w + a.w + b.w + bb.w, 0.f) * ww.w;
            }
            if (eid < E) out[eid] = s + bias2;
        }
        __syncwarp();  // A rows reused next iteration
    }
}

// ---------------------------------------------------------------------------
extern "C" void kernel_launch(void* const* d_in, const int* in_sizes, int n_in,
                              void* d_out, int out_size) {
    const float *nf = 0, *centroid = 0, *W1 = 0, *b1 = 0, *W2 = 0, *b2 = 0;
    const void* ei = 0;
    int nf_elems = 0, cen_elems = 0;
    int last_size1 = -1;

    for (int i = 0; i < n_in; i++) {
        int s = in_sizes[i];
        if (s == 1) { last_size1 = i; continue; }
        if (s == 128) {
            if (!b1) b1 = (const float*)d_in[i];
            else     W2 = (const float*)d_in[i];
            continue;
        }
        if (s == 2048) { centroid = (const float*)d_in[i]; cen_elems = s; continue; }
        if (s == 49152) { W1 = (const float*)d_in[i]; continue; }
        if (s == 2 * out_size) { ei = d_in[i]; continue; }
        if (s > nf_elems) { nf = (const float*)d_in[i]; nf_elems = s; }
    }
    if (last_size1 >= 0) b2 = (const float*)d_in[last_size1];

    const int E = out_size;
    const int n_nodes = nf_elems / DIM;
    const int bs = cen_elems / DIM;
    const int npg = n_nodes / (bs > 0 ? bs : 1);

    cudaFuncSetAttribute(precompute_kernel,
                         cudaFuncAttributeMaxDynamicSharedMemorySize, PRE_SMEM);
    precompute_kernel<<<(n_nodes + 127) / 128, 128, PRE_SMEM>>>(nf, centroid, W1,
                                                                n_nodes, npg);

    detect_idx_kernel<<<1, 256>>>((const unsigned int*)ei);

    int sms = 148;
    cudaDeviceGetAttribute(&sms, cudaDevAttrMultiProcessorCount, 0);

    cudaFuncSetAttribute(edge_kernel,
                         cudaFuncAttributeMaxDynamicSharedMemorySize, EDGE_SMEM);
    edge_kernel<<<sms, 128, EDGE_SMEM>>>(nf, ei, W1, b1, W2, b2, (float*)d_out, E);
}

// round 7
// speedup vs baseline: 1.0950x; 1.0950x over previous
#include <cuda_runtime.h>
#include <cuda_bf16.h>
#include <mma.h>
using namespace nvcuda;

#define DIM 128
#define MAX_NODES 65536

__device__ float g_Q[MAX_NODES * 256];
__device__ int g_idx64;

// ---------------------------------------------------------------------------
__global__ void detect_idx_kernel(const unsigned int* __restrict__ w) {
    __shared__ int s_any;
    if (threadIdx.x == 0) s_any = 0;
    __syncthreads();
    int found = 0;
    for (int i = threadIdx.x; i < 4096; i += blockDim.x)
        if (w[2 * i + 1] != 0u) found = 1;
    if (found) atomicOr(&s_any, 1);
    __syncthreads();
    if (threadIdx.x == 0) g_idx64 = (s_any == 0) ? 1 : 0;
}

// ---------------------------------------------------------------------------
__device__ __forceinline__ void split2(float v0, float v1, unsigned& h, unsigned& l) {
    __nv_bfloat162 hh = __floats2bfloat162_rn(v0, v1);
    float2 hf = __bfloat1622float2(hh);
    __nv_bfloat162 ll = __floats2bfloat162_rn(v0 - hf.x, v1 - hf.y);
    h = *(unsigned*)&hh;
    l = *(unsigned*)&ll;
}

typedef wmma::fragment<wmma::matrix_a, 16, 16, 16, __nv_bfloat16, wmma::row_major> FragA;
typedef wmma::fragment<wmma::matrix_b, 16, 16, 16, __nv_bfloat16, wmma::row_major> FragB;
typedef wmma::fragment<wmma::accumulator, 16, 16, 16, float> FragC;

// ---------------------------------------------------------------------------
// Precompute: Q[node][0:256] = (nf[node]-centroid[g]) @ [W1b | W1c]
// 128 nodes/CTA (contiguous rows -> fully coalesced loads), 8 warps, each
// warp owns 16 node rows. bf16-split (hh+hl+lh), fp32 acc direct to g_Q.
// ---------------------------------------------------------------------------
#define PRE_SMEM (128 * 264 * 2 * 2 + 128 * 136 * 2 * 2)

__global__ __launch_bounds__(256)
void precompute_kernel(const float* __restrict__ nf, const float* __restrict__ centroid,
                       const float* __restrict__ W1, int n_nodes, int npg) {
    extern __shared__ char sm[];
    __nv_bfloat16* sW_hi = (__nv_bfloat16*)sm;          // [128 k][264 n]
    __nv_bfloat16* sW_lo = sW_hi + 128 * 264;
    __nv_bfloat16* sA_hi = sW_lo + 128 * 264;           // [128 node][136 k]
    __nv_bfloat16* sA_lo = sA_hi + 128 * 136;

    const int t = threadIdx.x;
    const int base = blockIdx.x * 128;

    for (int i = t; i < 128 * 256; i += 256) {
        int k = i >> 8, n = i & 255;
        float w = (n < 128) ? W1[DIM * DIM + k * DIM + n]
                            : W1[2 * DIM * DIM + k * DIM + (n - 128)];
        __nv_bfloat16 hi = __float2bfloat16(w);
        __nv_bfloat16 lo = __float2bfloat16(w - __bfloat162float(hi));
        sW_hi[k * 264 + n] = hi;
        sW_lo[k * 264 + n] = lo;
    }
    __syncthreads();

    if (base + 128 > n_nodes) {   // scalar fallback for partial tile
        for (int node = base; node < n_nodes; node++) {
            const float* row = nf + (size_t)node * DIM;
            const float* cen = centroid + (size_t)(node / npg) * DIM;
            for (int c = t; c < 256; c += 256) {
                const float* wc = (c < 128) ? W1 + DIM * DIM + c
                                            : W1 + 2 * DIM * DIM + (c - 128);
                float acc = 0.f;
                for (int k = 0; k < DIM; k++) acc += (row[k] - cen[k]) * wc[k * DIM];
                g_Q[(size_t)node * 256 + c] = acc;
            }
        }
        return;
    }

    // residuals: contiguous 64KB block, perfectly coalesced float4 loads
    for (int i = t; i < 128 * 32; i += 256) {
        int node = i >> 5, c4 = i & 31;
        float4 v = ((const float4*)nf)[(size_t)(base + node) * 32 + c4];
        float4 c = ((const float4*)centroid)[(size_t)((base + node) / npg) * 32 + c4];
        unsigned h0, l0, h1, l1;
        split2(v.x - c.x, v.y - c.y, h0, l0);
        split2(v.z - c.z, v.w - c.w, h1, l1);
        unsigned* rh = (unsigned*)(sA_hi + node * 136);
        unsigned* rl = (unsigned*)(sA_lo + node * 136);
        rh[2 * c4] = h0; rh[2 * c4 + 1] = h1;
        rl[2 * c4] = l0; rl[2 * c4 + 1] = l1;
    }
    __syncthreads();

    const int w = t >> 5;
    const __nv_bfloat16* Ah = sA_hi + (w * 16) * 136;
#pragma unroll 1
    for (int chunk = 0; chunk < 4; chunk++) {
        FragC acc[4];
#pragma unroll
        for (int n = 0; n < 4; n++) wmma::fill_fragment(acc[n], 0.f);
#pragma unroll
        for (int k = 0; k < 8; k++) {
            FragA a_hi, a_lo;
            wmma::load_matrix_sync(a_hi, Ah + k * 16, 136);
            wmma::load_matrix_sync(a_lo, Ah + 128 * 136 + k * 16, 136);
#pragma unroll
            for (int n = 0; n < 4; n++) {
                FragB b_hi, b_lo;
                const __nv_bfloat16* bp = sW_hi + (k * 16) * 264 + chunk * 64 + n * 16;
                wmma::load_matrix_sync(b_hi, bp, 264);
                wmma::load_matrix_sync(b_lo, bp + 128 * 264, 264);
                wmma::mma_sync(acc[n], a_hi, b_hi, acc[n]);
                wmma::mma_sync(acc[n], a_hi, b_lo, acc[n]);
                wmma::mma_sync(acc[n], a_lo, b_hi, acc[n]);
            }
        }
#pragma unroll
        for (int n = 0; n < 4; n++)
            wmma::store_matrix_sync(
                g_Q + (size_t)(base + w * 16) * 256 + chunk * 64 + n * 16,
                acc[n], 256, wmma::mem_row_major);
    }
}

// ---------------------------------------------------------------------------
// Edge kernel: 256 threads / 8 independent warps. Warp processes 16-edge
// chunks (grid-strided by total warp count). Per chunk:
//   coalesced gather |nf[dst]-nf[src]| -> bf16 hi/lo rows (warp-private)
//   H = A @ W1a  (wmma bf16-split, 1 m-tile x 8 n-tiles)
//   coalesced epilogue: relu(H + Q[dst] + Q[src][128:] + b1) . W2 + b2
// No __syncthreads in the loop.
// ---------------------------------------------------------------------------
#define EDGE_SMEM (128 * 136 * 2 * 2 + 128 * 136 * 2 * 2 + 128 * 132 * 4 + 1024)

__global__ __launch_bounds__(256, 1)
void edge_kernel(const float* __restrict__ nf, const void* __restrict__ ei,
                 const float* __restrict__ W1, const float* __restrict__ b1,
                 const float* __restrict__ W2, const float* __restrict__ b2,
                 float* __restrict__ out, int E) {
    extern __shared__ char sm[];
    __nv_bfloat16* sW_hi = (__nv_bfloat16*)sm;          // [128 k][136 n]
    __nv_bfloat16* sW_lo = sW_hi + 128 * 136;
    __nv_bfloat16* sA_hi = sW_lo + 128 * 136;           // [128 e][136 k]
    __nv_bfloat16* sA_lo = sA_hi + 128 * 136;
    float* sOut = (float*)(sA_lo + 128 * 136);          // [128 e][132 n]
    float* sB1  = sOut + 128 * 132;
    float* sW2  = sB1 + 128;

    const int t = threadIdx.x;
    for (int i = t; i < DIM * DIM; i += 256) {
        float v = W1[i];   // W1a block: [k][n]
        __nv_bfloat16 hi = __float2bfloat16(v);
        __nv_bfloat16 lo = __float2bfloat16(v - __bfloat162float(hi));
        int k = i >> 7, n = i & 127;
        sW_hi[k * 136 + n] = hi;
        sW_lo[k * 136 + n] = lo;
    }
    if (t < DIM) { sB1[t] = b1[t]; sW2[t] = W2[t]; }
    __syncthreads();

    const int w = t >> 5;
    const int lane = t & 31;
    __nv_bfloat16* Ah = sA_hi + (w * 16) * 136;
    __nv_bfloat16* Al = sA_lo + (w * 16) * 136;
    float* orow0 = sOut + (w * 16) * 132;

    float b1r[4], w2r[4];
#pragma unroll
    for (int r = 0; r < 4; r++) { b1r[r] = sB1[lane + 32 * r]; w2r[r] = sW2[lane + 32 * r]; }
    const float bias2 = b2[0];

    const int mode64 = g_idx64;
    const long long* ei64 = (const long long*)ei;
    const int* ei32 = (const int*)ei;

    const int chunks = (E + 15) >> 4;
    const int nwarps = gridDim.x * 8;
    for (int ch = blockIdx.x * 8 + w; ch < chunks; ch += nwarps) {
        const int e0 = ch * 16;

        // indices: lanes 0-15 hold src, lanes 16-31 hold dst of edges e0..e0+15
        int idxv = 0;
        {
            int eidL = e0 + (lane & 15);
            if (eidL < E) {
                if (mode64) idxv = (lane < 16) ? (int)ei64[eidL] : (int)ei64[E + eidL];
                else        idxv = (lane < 16) ? ei32[eidL]      : ei32[E + eidL];
            }
        }

        // coalesced gather: per edge, lanes span columns (float2 each)
#pragma unroll 4
        for (int i = 0; i < 16; i++) {
            int sv = __shfl_sync(0xffffffffu, idxv, i);
            int dv = __shfl_sync(0xffffffffu, idxv, 16 + i);
            const float2* pi = (const float2*)(nf + (size_t)dv * DIM);
            const float2* pj = (const float2*)(nf + (size_t)sv * DIM);
            float2 a0 = pi[lane],      c0 = pj[lane];
            float2 a1 = pi[lane + 32], c1 = pj[lane + 32];
            unsigned h0, l0, h1, l1;
            split2(fabsf(a0.x - c0.x), fabsf(a0.y - c0.y), h0, l0);
            split2(fabsf(a1.x - c1.x), fabsf(a1.y - c1.y), h1, l1);
            unsigned* rh = (unsigned*)(Ah + i * 136);
            unsigned* rl = (unsigned*)(Al + i * 136);
            rh[lane] = h0; rh[lane + 32] = h1;
            rl[lane] = l0; rl[lane + 32] = l1;
        }
        __syncwarp();

        // H = A(16x128) @ W1a(128x128): bf16-split wmma
#pragma unroll 1
        for (int nh = 0; nh < 2; nh++) {
            FragC acc[4];
#pragma unroll
            for (int n = 0; n < 4; n++) wmma::fill_fragment(acc[n], 0.f);
#pragma unroll
            for (int k = 0; k < 8; k++) {
                FragA a_hi, a_lo;
                wmma::load_matrix_sync(a_hi, Ah + k * 16, 136);
                wmma::load_matrix_sync(a_lo, Al + k * 16, 136);
#pragma unroll
                for (int n = 0; n < 4; n++) {
                    FragB b_hi, b_lo;
                    const __nv_bfloat16* bp = sW_hi + (k * 16) * 136 + nh * 64 + n * 16;
                    wmma::load_matrix_sync(b_hi, bp, 136);
                    wmma::load_matrix_sync(b_lo, bp + 128 * 136, 136);
                    wmma::mma_sync(acc[n], a_hi, b_hi, acc[n]);
                    wmma::mma_sync(acc[n], a_hi, b_lo, acc[n]);
                    wmma::mma_sync(acc[n], a_lo, b_hi, acc[n]);
                }
            }
#pragma unroll
            for (int n = 0; n < 4; n++)
                wmma::store_matrix_sync(orow0 + nh * 64 + n * 16, acc[n], 132,
                                        wmma::mem_row_major);
        }
        __syncwarp();

        // coalesced epilogue: lanes span Q/H columns; warp-reduce per edge
#pragma unroll 2
        for (int i = 0; i < 16; i++) {
            int sv = __shfl_sync(0xffffffffu, idxv, i);
            int dv = __shfl_sync(0xffffffffu, idxv, 16 + i);
            const float* qd = g_Q + (size_t)dv * 256;
            const float* qs = g_Q + (size_t)sv * 256 + 128;
            const float* orow = orow0 + i * 132;
            float s = 0.f;
#pragma unroll
            for (int r = 0; r < 4; r++) {
                int c = lane + 32 * r;
                float h = orow[c] + qd[c] + qs[c] + b1r[r];
                s += fmaxf(h, 0.f) * w2r[r];
            }
#pragma unroll
            for (int off = 16; off > 0; off >>= 1)
                s += __shfl_down_sync(0xffffffffu, s, off);
            if (lane == 0 && e0 + i < E) out[e0 + i] = s + bias2;
        }
        __syncwarp();
    }
}

// ---------------------------------------------------------------------------
extern "C" void kernel_launch(void* const* d_in, const int* in_sizes, int n_in,
                              void* d_out, int out_size) {
    const float *nf = 0, *centroid = 0, *W1 = 0, *b1 = 0, *W2 = 0, *b2 = 0;
    const void* ei = 0;
    int nf_elems = 0, cen_elems = 0;
    int last_size1 = -1;

    for (int i = 0; i < n_in; i++) {
        int s = in_sizes[i];
        if (s == 1) { last_size1 = i; continue; }
        if (s == 128) {
            if (!b1) b1 = (const float*)d_in[i];
            else     W2 = (const float*)d_in[i];
            continue;
        }
        if (s == 2048) { centroid = (const float*)d_in[i]; cen_elems = s; continue; }
        if (s == 49152) { W1 = (const float*)d_in[i]; continue; }
        if (s == 2 * out_size) { ei = d_in[i]; continue; }
        if (s > nf_elems) { nf = (const float*)d_in[i]; nf_elems = s; }
    }
    if (last_size1 >= 0) b2 = (const float*)d_in[last_size1];

    const int E = out_size;
    const int n_nodes = nf_elems / DIM;
    const int bs = cen_elems / DIM;
    const int npg = n_nodes / (bs > 0 ? bs : 1);

    cudaFuncSetAttribute(precompute_kernel,
                         cudaFuncAttributeMaxDynamicSharedMemorySize, PRE_SMEM);
    precompute_kernel<<<(n_nodes + 127) / 128, 256, PRE_SMEM>>>(nf, centroid, W1,
                                                                n_nodes, npg);

    detect_idx_kernel<<<1, 256>>>((const unsigned int*)ei);

    int sms = 148;
    cudaDeviceGetAttribute(&sms, cudaDevAttrMultiProcessorCount, 0);

    cudaFuncSetAttribute(edge_kernel,
                         cudaFuncAttributeMaxDynamicSharedMemorySize, EDGE_SMEM);
    edge_kernel<<<sms, 256, EDGE_SMEM>>>(nf, ei, W1, b1, W2, b2, (float*)d_out, E);
}

// round 8
// speedup vs baseline: 1.3679x; 1.2493x over previous
#include <cuda_runtime.h>
#include <cuda_bf16.h>
#include <mma.h>
using namespace nvcuda;

#define DIM 128
#define MAX_NODES 65536

__device__ float g_Q[MAX_NODES * 256];
__device__ int g_idx64;

// ---------------------------------------------------------------------------
__global__ void detect_idx_kernel(const unsigned int* __restrict__ w) {
    __shared__ int s_any;
    if (threadIdx.x == 0) s_any = 0;
    __syncthreads();
    int found = 0;
    for (int i = threadIdx.x; i < 4096; i += blockDim.x)
        if (w[2 * i + 1] != 0u) found = 1;
    if (found) atomicOr(&s_any, 1);
    __syncthreads();
    if (threadIdx.x == 0) g_idx64 = (s_any == 0) ? 1 : 0;
}

// ---------------------------------------------------------------------------
__device__ __forceinline__ void split2(float v0, float v1, unsigned& h, unsigned& l) {
    __nv_bfloat162 hh = __floats2bfloat162_rn(v0, v1);
    float2 hf = __bfloat1622float2(hh);
    __nv_bfloat162 ll = __floats2bfloat162_rn(v0 - hf.x, v1 - hf.y);
    h = *(unsigned*)&hh;
    l = *(unsigned*)&ll;
}

typedef wmma::fragment<wmma::matrix_a, 16, 16, 16, __nv_bfloat16, wmma::row_major> FragA;
typedef wmma::fragment<wmma::matrix_b, 16, 16, 16, __nv_bfloat16, wmma::row_major> FragB;
typedef wmma::fragment<wmma::accumulator, 16, 16, 16, float> FragC;

// ---------------------------------------------------------------------------
// Precompute: Q[node][0:256] = (nf[node]-centroid[g]) @ [W1b | W1c]
// 128 nodes/CTA, 512 threads / 16 warps. 32 tasks = 8 m-tiles x 4 n-chunks;
// warp w does tasks w and w+16. bf16-split, fp32 acc direct to g_Q.
// ---------------------------------------------------------------------------
#define PRE_SMEM (128 * 264 * 2 * 2 + 128 * 136 * 2 * 2)

__global__ __launch_bounds__(512)
void precompute_kernel(const float* __restrict__ nf, const float* __restrict__ centroid,
                       const float* __restrict__ W1, int n_nodes, int npg) {
    extern __shared__ char sm[];
    __nv_bfloat16* sW_hi = (__nv_bfloat16*)sm;          // [128 k][264 n]
    __nv_bfloat16* sW_lo = sW_hi + 128 * 264;
    __nv_bfloat16* sA_hi = sW_lo + 128 * 264;           // [128 node][136 k]
    __nv_bfloat16* sA_lo = sA_hi + 128 * 136;

    const int t = threadIdx.x;
    const int base = blockIdx.x * 128;

    for (int i = t; i < 128 * 256; i += 512) {
        int k = i >> 8, n = i & 255;
        float w = (n < 128) ? W1[DIM * DIM + k * DIM + n]
                            : W1[2 * DIM * DIM + k * DIM + (n - 128)];
        __nv_bfloat16 hi = __float2bfloat16(w);
        __nv_bfloat16 lo = __float2bfloat16(w - __bfloat162float(hi));
        sW_hi[k * 264 + n] = hi;
        sW_lo[k * 264 + n] = lo;
    }
    __syncthreads();

    if (base + 128 > n_nodes) {   // scalar fallback for partial tile
        for (int node = base; node < n_nodes; node++) {
            const float* row = nf + (size_t)node * DIM;
            const float* cen = centroid + (size_t)(node / npg) * DIM;
            for (int c = t; c < 256; c += 512) {
                const float* wc = (c < 128) ? W1 + DIM * DIM + c
                                            : W1 + 2 * DIM * DIM + (c - 128);
                float acc = 0.f;
                for (int k = 0; k < DIM; k++) acc += (row[k] - cen[k]) * wc[k * DIM];
                g_Q[(size_t)node * 256 + c] = acc;
            }
        }
        return;
    }

    // residuals: contiguous block, coalesced float4 loads
    for (int i = t; i < 128 * 32; i += 512) {
        int node = i >> 5, c4 = i & 31;
        float4 v = ((const float4*)nf)[(size_t)(base + node) * 32 + c4];
        float4 c = ((const float4*)centroid)[(size_t)((base + node) / npg) * 32 + c4];
        unsigned h0, l0, h1, l1;
        split2(v.x - c.x, v.y - c.y, h0, l0);
        split2(v.z - c.z, v.w - c.w, h1, l1);
        unsigned* rh = (unsigned*)(sA_hi + node * 136);
        unsigned* rl = (unsigned*)(sA_lo + node * 136);
        rh[2 * c4] = h0; rh[2 * c4 + 1] = h1;
        rl[2 * c4] = l0; rl[2 * c4 + 1] = l1;
    }
    __syncthreads();

    const int w = t >> 5;
#pragma unroll
    for (int task = w; task < 32; task += 16) {
        const int m = task & 7;
        const int chunk = task >> 3;
        const __nv_bfloat16* Ah = sA_hi + (m * 16) * 136;
        FragC acc[4];
#pragma unroll
        for (int n = 0; n < 4; n++) wmma::fill_fragment(acc[n], 0.f);
#pragma unroll
        for (int k = 0; k < 8; k++) {
            FragA a_hi, a_lo;
            wmma::load_matrix_sync(a_hi, Ah + k * 16, 136);
            wmma::load_matrix_sync(a_lo, Ah + 128 * 136 + k * 16, 136);
#pragma unroll
            for (int n = 0; n < 4; n++) {
                FragB b_hi, b_lo;
                const __nv_bfloat16* bp = sW_hi + (k * 16) * 264 + chunk * 64 + n * 16;
                wmma::load_matrix_sync(b_hi, bp, 264);
                wmma::load_matrix_sync(b_lo, bp + 128 * 264, 264);
                wmma::mma_sync(acc[n], a_hi, b_hi, acc[n]);
                wmma::mma_sync(acc[n], a_hi, b_lo, acc[n]);
                wmma::mma_sync(acc[n], a_lo, b_hi, acc[n]);
            }
        }
#pragma unroll
        for (int n = 0; n < 4; n++)
            wmma::store_matrix_sync(
                g_Q + (size_t)(base + m * 16) * 256 + chunk * 64 + n * 16,
                acc[n], 256, wmma::mem_row_major);
    }
}

// ---------------------------------------------------------------------------
// Edge kernel: 512 threads / 16 warps, CTA-cooperative 128-edge tiles.
//   phase 1: indices -> smem
//   phase 2: warp w gathers edges [8w, 8w+8): |nf[dst]-nf[src]| bf16 hi/lo
//   phase 3: warp w computes output tile (m = w&7, n-half = w>>3)
//   phase 4: warp w epilogues edges [8w, 8w+8): relu(H+Q+b1).W2 + b2
// ---------------------------------------------------------------------------
#define EDGE_SMEM (128 * 136 * 2 * 2 + 128 * 136 * 2 * 2 + 128 * 132 * 4 + 2048)

__global__ __launch_bounds__(512, 1)
void edge_kernel(const float* __restrict__ nf, const void* __restrict__ ei,
                 const float* __restrict__ W1, const float* __restrict__ b1,
                 const float* __restrict__ W2, const float* __restrict__ b2,
                 float* __restrict__ out, int E) {
    extern __shared__ char sm[];
    __nv_bfloat16* sW_hi = (__nv_bfloat16*)sm;          // [128 k][136 n]
    __nv_bfloat16* sW_lo = sW_hi + 128 * 136;
    __nv_bfloat16* sA_hi = sW_lo + 128 * 136;           // [128 e][136 k]
    __nv_bfloat16* sA_lo = sA_hi + 128 * 136;
    float* sOut = (float*)(sA_lo + 128 * 136);          // [128 e][132 n]
    float* sB1  = sOut + 128 * 132;                     // 128
    float* sW2  = sB1 + 128;                            // 128
    int* sSrc   = (int*)(sW2 + 128);                    // 128
    int* sDst   = sSrc + 128;                           // 128

    const int t = threadIdx.x;
    for (int i = t; i < DIM * DIM; i += 512) {
        float v = W1[i];   // W1a block: [k][n]
        __nv_bfloat16 hi = __float2bfloat16(v);
        __nv_bfloat16 lo = __float2bfloat16(v - __bfloat162float(hi));
        int k = i >> 7, n = i & 127;
        sW_hi[k * 136 + n] = hi;
        sW_lo[k * 136 + n] = lo;
    }
    if (t < DIM) { sB1[t] = b1[t]; sW2[t] = W2[t]; }
    __syncthreads();

    const int w = t >> 5;
    const int lane = t & 31;
    const int m = w & 7;        // MMA m-tile
    const int nh = w >> 3;      // MMA n-half

    float b1r[4], w2r[4];
#pragma unroll
    for (int r = 0; r < 4; r++) { b1r[r] = sB1[lane + 32 * r]; w2r[r] = sW2[lane + 32 * r]; }
    const float bias2 = b2[0];

    const int mode64 = g_idx64;
    const long long* ei64 = (const long long*)ei;
    const int* ei32 = (const int*)ei;

    const int tiles = (E + 127) >> 7;
    for (int tile = blockIdx.x; tile < tiles; tile += gridDim.x) {
        // phase 1: indices
        if (t < 256) {
            int e = (t & 127);
            int eid = tile * 128 + e;
            int v = 0;
            if (eid < E) {
                if (t < 128) v = mode64 ? (int)ei64[eid] : ei32[eid];
                else         v = mode64 ? (int)ei64[E + eid] : ei32[E + eid];
            }
            if (t < 128) sSrc[e] = v; else sDst[e] = v;
        }
        __syncthreads();

        // phase 2: gather 8 edges per warp, lanes span columns
#pragma unroll
        for (int i = 0; i < 8; i++) {
            int e = 8 * w + i;
            int sv = sSrc[e], dv = sDst[e];
            const float2* pi = (const float2*)(nf + (size_t)dv * DIM);
            const float2* pj = (const float2*)(nf + (size_t)sv * DIM);
            float2 a0 = pi[lane],      c0 = pj[lane];
            float2 a1 = pi[lane + 32], c1 = pj[lane + 32];
            unsigned h0, l0, h1, l1;
            split2(fabsf(a0.x - c0.x), fabsf(a0.y - c0.y), h0, l0);
            split2(fabsf(a1.x - c1.x), fabsf(a1.y - c1.y), h1, l1);
            unsigned* rh = (unsigned*)(sA_hi + e * 136);
            unsigned* rl = (unsigned*)(sA_lo + e * 136);
            rh[lane] = h0; rh[lane + 32] = h1;
            rl[lane] = l0; rl[lane + 32] = l1;
        }
        __syncthreads();

        // phase 3: MMA — warp computes (m-tile, n-half): 16 x 64 output
        {
            const __nv_bfloat16* Ah = sA_hi + (m * 16) * 136;
            FragC acc[4];
#pragma unroll
            for (int n = 0; n < 4; n++) wmma::fill_fragment(acc[n], 0.f);
#pragma unroll
            for (int k = 0; k < 8; k++) {
                FragA a_hi, a_lo;
                wmma::load_matrix_sync(a_hi, Ah + k * 16, 136);
                wmma::load_matrix_sync(a_lo, Ah + 128 * 136 + k * 16, 136);
#pragma unroll
                for (int n = 0; n < 4; n++) {
                    FragB b_hi, b_lo;
                    const __nv_bfloat16* bp = sW_hi + (k * 16) * 136 + nh * 64 + n * 16;
                    wmma::load_matrix_sync(b_hi, bp, 136);
                    wmma::load_matrix_sync(b_lo, bp + 128 * 136, 136);
                    wmma::mma_sync(acc[n], a_hi, b_hi, acc[n]);
                    wmma::mma_sync(acc[n], a_hi, b_lo, acc[n]);
                    wmma::mma_sync(acc[n], a_lo, b_hi, acc[n]);
                }
            }
#pragma unroll
            for (int n = 0; n < 4; n++)
                wmma::store_matrix_sync(sOut + (m * 16) * 132 + nh * 64 + n * 16,
                                        acc[n], 132, wmma::mem_row_major);
        }
        __syncthreads();

        // phase 4: epilogue — 8 edges per warp, coalesced columns
#pragma unroll
        for (int i = 0; i < 8; i++) {
            int e = 8 * w + i;
            int eid = tile * 128 + e;
            int sv = sSrc[e], dv = sDst[e];
            const float* qd = g_Q + (size_t)dv * 256;
            const float* qs = g_Q + (size_t)sv * 256 + 128;
            const float* orow = sOut + e * 132;
            float s = 0.f;
#pragma unroll
            for (int r = 0; r < 4; r++) {
                int c = lane + 32 * r;
                float h = orow[c] + qd[c] + qs[c] + b1r[r];
                s += fmaxf(h, 0.f) * w2r[r];
            }
#pragma unroll
            for (int off = 16; off > 0; off >>= 1)
                s += __shfl_down_sync(0xffffffffu, s, off);
            if (lane == 0 && eid < E) out[eid] = s + bias2;
        }
        __syncthreads();
    }
}

// ---------------------------------------------------------------------------
extern "C" void kernel_launch(void* const* d_in, const int* in_sizes, int n_in,
                              void* d_out, int out_size) {
    const float *nf = 0, *centroid = 0, *W1 = 0, *b1 = 0, *W2 = 0, *b2 = 0;
    const void* ei = 0;
    int nf_elems = 0, cen_elems = 0;
    int last_size1 = -1;

    for (int i = 0; i < n_in; i++) {
        int s = in_sizes[i];
        if (s == 1) { last_size1 = i; continue; }
        if (s == 128) {
            if (!b1) b1 = (const float*)d_in[i];
            else     W2 = (const float*)d_in[i];
            continue;
        }
        if (s == 2048) { centroid = (const float*)d_in[i]; cen_elems = s; continue; }
        if (s == 49152) { W1 = (const float*)d_in[i]; continue; }
        if (s == 2 * out_size) { ei = d_in[i]; continue; }
        if (s > nf_elems) { nf = (const float*)d_in[i]; nf_elems = s; }
    }
    if (last_size1 >= 0) b2 = (const float*)d_in[last_size1];

    const int E = out_size;
    const int n_nodes = nf_elems / DIM;
    const int bs = cen_elems / DIM;
    const int npg = n_nodes / (bs > 0 ? bs : 1);

    cudaFuncSetAttribute(precompute_kernel,
                         cudaFuncAttributeMaxDynamicSharedMemorySize, PRE_SMEM);
    precompute_kernel<<<(n_nodes + 127) / 128, 512, PRE_SMEM>>>(nf, centroid, W1,
                                                                n_nodes, npg);

    detect_idx_kernel<<<1, 256>>>((const unsigned int*)ei);

    int sms = 148;
    cudaDeviceGetAttribute(&sms, cudaDevAttrMultiProcessorCount, 0);

    cudaFuncSetAttribute(edge_kernel,
                         cudaFuncAttributeMaxDynamicSharedMemorySize, EDGE_SMEM);
    edge_kernel<<<sms, 512, EDGE_SMEM>>>(nf, ei, W1, b1, W2, b2, (float*)d_out, E);
}

// round 9
// speedup vs baseline: 1.5063x; 1.1012x over previous
#include <cuda_runtime.h>
#include <cuda_bf16.h>
#include <mma.h>
using namespace nvcuda;

#define DIM 128
#define MAX_NODES 65536

__device__ float g_Q[MAX_NODES * 256];
__device__ int g_idx64;

// ---------------------------------------------------------------------------
__global__ void detect_idx_kernel(const unsigned int* __restrict__ w) {
    __shared__ int s_any;
    if (threadIdx.x == 0) s_any = 0;
    __syncthreads();
    int found = 0;
    for (int i = threadIdx.x; i < 4096; i += blockDim.x)
        if (w[2 * i + 1] != 0u) found = 1;
    if (found) atomicOr(&s_any, 1);
    __syncthreads();
    if (threadIdx.x == 0) g_idx64 = (s_any == 0) ? 1 : 0;
}

// ---------------------------------------------------------------------------
__device__ __forceinline__ void split2(float v0, float v1, unsigned& h, unsigned& l) {
    __nv_bfloat162 hh = __floats2bfloat162_rn(v0, v1);
    float2 hf = __bfloat1622float2(hh);
    __nv_bfloat162 ll = __floats2bfloat162_rn(v0 - hf.x, v1 - hf.y);
    h = *(unsigned*)&hh;
    l = *(unsigned*)&ll;
}

typedef wmma::fragment<wmma::matrix_a, 16, 16, 16, __nv_bfloat16, wmma::row_major> FragA;
typedef wmma::fragment<wmma::matrix_b, 16, 16, 16, __nv_bfloat16, wmma::row_major> FragB;
typedef wmma::fragment<wmma::accumulator, 16, 16, 16, float> FragC;

// ---------------------------------------------------------------------------
// Precompute: CTA = (64-node tile, n-half). Q[node][half*128 + 0:128] =
// residual @ W1{b,c}. W half 69.6KB + A 34.8KB = 104.4KB -> 2 CTA/SM.
// 16 warps: warp w -> m-tile (w&3), n-pair (w>>2). Acc direct to g_Q.
// ---------------------------------------------------------------------------
#define PRE_SMEM (128 * 136 * 2 * 2 + 64 * 136 * 2 * 2)

__global__ __launch_bounds__(512, 2)
void precompute_kernel(const float* __restrict__ nf, const float* __restrict__ centroid,
                       const float* __restrict__ W1, int n_nodes, int npg) {
    extern __shared__ char sm[];
    __nv_bfloat16* sW_hi = (__nv_bfloat16*)sm;          // [128 k][136 n]
    __nv_bfloat16* sW_lo = sW_hi + 128 * 136;
    __nv_bfloat16* sA_hi = sW_lo + 128 * 136;           // [64 node][136 k]
    __nv_bfloat16* sA_lo = sA_hi + 64 * 136;

    const int t = threadIdx.x;
    const int half = blockIdx.x & 1;
    const int base = (blockIdx.x >> 1) * 64;

    // stage W half: W1b (half 0) or W1c (half 1), [k][n] -> bf16 hi/lo
    const float* Wsrc = W1 + (1 + half) * DIM * DIM;
    for (int i = t; i < 128 * 128; i += 512) {
        int k = i >> 7, n = i & 127;
        float w = Wsrc[i];
        __nv_bfloat16 hi = __float2bfloat16(w);
        __nv_bfloat16 lo = __float2bfloat16(w - __bfloat162float(hi));
        sW_hi[k * 136 + n] = hi;
        sW_lo[k * 136 + n] = lo;
    }
    __syncthreads();

    if (base + 64 > n_nodes) {   // scalar fallback for partial tile
        for (int node = base; node < n_nodes; node++) {
            const float* row = nf + (size_t)node * DIM;
            const float* cen = centroid + (size_t)(node / npg) * DIM;
            for (int c = t; c < 128; c += 512) {
                const float* wc = Wsrc + c;
                float acc = 0.f;
                for (int k = 0; k < DIM; k++) acc += (row[k] - cen[k]) * wc[k * DIM];
                g_Q[(size_t)node * 256 + half * 128 + c] = acc;
            }
        }
        return;
    }

    // residuals: coalesced float4 loads, split to bf16 hi/lo
    for (int i = t; i < 64 * 32; i += 512) {
        int node = i >> 5, c4 = i & 31;
        float4 v = ((const float4*)nf)[(size_t)(base + node) * 32 + c4];
        float4 c = ((const float4*)centroid)[(size_t)((base + node) / npg) * 32 + c4];
        unsigned h0, l0, h1, l1;
        split2(v.x - c.x, v.y - c.y, h0, l0);
        split2(v.z - c.z, v.w - c.w, h1, l1);
        unsigned* rh = (unsigned*)(sA_hi + node * 136);
        unsigned* rl = (unsigned*)(sA_lo + node * 136);
        rh[2 * c4] = h0; rh[2 * c4 + 1] = h1;
        rl[2 * c4] = l0; rl[2 * c4 + 1] = l1;
    }
    __syncthreads();

    const int w = t >> 5;
    const int m = w & 3;
    const int np = w >> 2;   // n-pair: cols [np*32, np*32+32)
    const __nv_bfloat16* Ah = sA_hi + (m * 16) * 136;
    const __nv_bfloat16* Al = sA_lo + (m * 16) * 136;

    FragC acc[2];
#pragma unroll
    for (int n = 0; n < 2; n++) wmma::fill_fragment(acc[n], 0.f);
#pragma unroll
    for (int k = 0; k < 8; k++) {
        FragA a_hi, a_lo;
        wmma::load_matrix_sync(a_hi, Ah + k * 16, 136);
        wmma::load_matrix_sync(a_lo, Al + k * 16, 136);
#pragma unroll
        for (int n = 0; n < 2; n++) {
            FragB b_hi, b_lo;
            const __nv_bfloat16* bp = sW_hi + (k * 16) * 136 + np * 32 + n * 16;
            wmma::load_matrix_sync(b_hi, bp, 136);
            wmma::load_matrix_sync(b_lo, bp + 128 * 136, 136);
            wmma::mma_sync(acc[n], a_hi, b_hi, acc[n]);
            wmma::mma_sync(acc[n], a_hi, b_lo, acc[n]);
            wmma::mma_sync(acc[n], a_lo, b_hi, acc[n]);
        }
    }
#pragma unroll
    for (int n = 0; n < 2; n++)
        wmma::store_matrix_sync(
            g_Q + (size_t)(base + m * 16) * 256 + half * 128 + np * 32 + n * 16,
            acc[n], 256, wmma::mem_row_major);
}

// ---------------------------------------------------------------------------
// Edge kernel: 512 thr / 16 warps, 64-edge tiles, sOut ALIASED onto A region
// (A dead after MMA-read phase). 105.5KB smem -> 2 CTA/SM (32 warps).
//   gather: warp w owns edges 4w..4w+3, float4 loads (1 LDG.128/row)
//   MMA: warp w -> m-tile (w&3), n-pair (w>>2); acc in regs across the
//        A->sOut handover sync
//   epilogue: warp w epilogues its 4 edges, all-float4
// ---------------------------------------------------------------------------
#define EDGE_SMEM (128 * 136 * 2 * 2 + 64 * 136 * 2 * 2 + 1024)

__global__ __launch_bounds__(512, 2)
void edge_kernel(const float* __restrict__ nf, const void* __restrict__ ei,
                 const float* __restrict__ W1, const float* __restrict__ b1,
                 const float* __restrict__ W2, const float* __restrict__ b2,
                 float* __restrict__ out, int E) {
    extern __shared__ char sm[];
    __nv_bfloat16* sW_hi = (__nv_bfloat16*)sm;          // [128 k][136 n]
    __nv_bfloat16* sW_lo = sW_hi + 128 * 136;
    char* sU = (char*)(sW_lo + 128 * 136);              // union region
    __nv_bfloat16* sA_hi = (__nv_bfloat16*)sU;          // [64 e][136 k]
    __nv_bfloat16* sA_lo = sA_hi + 64 * 136;
    float* sOut = (float*)sU;                           // [64 e][132 n] (alias)
    float* sB1 = (float*)(sU + 64 * 136 * 2 * 2);       // 128
    float* sW2 = sB1 + 128;                             // 128

    const int t = threadIdx.x;
    for (int i = t; i < DIM * DIM; i += 512) {
        float v = W1[i];   // W1a block: [k][n]
        __nv_bfloat16 hi = __float2bfloat16(v);
        __nv_bfloat16 lo = __float2bfloat16(v - __bfloat162float(hi));
        int k = i >> 7, n = i & 127;
        sW_hi[k * 136 + n] = hi;
        sW_lo[k * 136 + n] = lo;
    }
    if (t < DIM) { sB1[t] = b1[t]; sW2[t] = W2[t]; }
    __syncthreads();

    const int w = t >> 5;
    const int lane = t & 31;
    const int m = w & 3;       // MMA m-tile
    const int np = w >> 2;     // MMA n-pair (32 cols)

    const float4 b1v = ((const float4*)sB1)[lane];
    const float4 w2v = ((const float4*)sW2)[lane];
    const float bias2 = b2[0];

    const int mode64 = g_idx64;
    const long long* ei64 = (const long long*)ei;
    const int* ei32 = (const int*)ei;

    const int tiles = (E + 63) >> 6;
    for (int tile = blockIdx.x; tile < tiles; tile += gridDim.x) {
        const int eb = tile * 64;

        // indices for this warp's 4 edges: lanes 0-3 src, lanes 4-7 dst
        int myi = 0;
        if (lane < 8) {
            int eidL = eb + 4 * w + (lane & 3);
            if (eidL < E) {
                size_t off = (lane < 4) ? (size_t)eidL : (size_t)E + eidL;
                myi = mode64 ? (int)ei64[off] : ei32[off];
            }
        }

        // gather: edge rows 4w..4w+3; lane covers cols 4*lane..4*lane+3
#pragma unroll
        for (int i = 0; i < 4; i++) {
            int sv = __shfl_sync(0xffffffffu, myi, i);
            int dv = __shfl_sync(0xffffffffu, myi, 4 + i);
            float4 a = ((const float4*)(nf + (size_t)dv * DIM))[lane];
            float4 b = ((const float4*)(nf + (size_t)sv * DIM))[lane];
            unsigned h0, l0, h1, l1;
            split2(fabsf(a.x - b.x), fabsf(a.y - b.y), h0, l0);
            split2(fabsf(a.z - b.z), fabsf(a.w - b.w), h1, l1);
            int e = 4 * w + i;
            ((uint2*)(sA_hi + e * 136))[lane] = make_uint2(h0, h1);
            ((uint2*)(sA_lo + e * 136))[lane] = make_uint2(l0, l1);
        }
        __syncthreads();

        // MMA into register fragments (A still live in smem)
        FragC acc[2];
#pragma unroll
        for (int n = 0; n < 2; n++) wmma::fill_fragment(acc[n], 0.f);
        {
            const __nv_bfloat16* Ah = sA_hi + (m * 16) * 136;
            const __nv_bfloat16* Al = sA_lo + (m * 16) * 136;
#pragma unroll
            for (int k = 0; k < 8; k++) {
                FragA a_hi, a_lo;
                wmma::load_matrix_sync(a_hi, Ah + k * 16, 136);
                wmma::load_matrix_sync(a_lo, Al + k * 16, 136);
#pragma unroll
                for (int n = 0; n < 2; n++) {
                    FragB b_hi, b_lo;
                    const __nv_bfloat16* bp = sW_hi + (k * 16) * 136 + np * 32 + n * 16;
                    wmma::load_matrix_sync(b_hi, bp, 136);
                    wmma::load_matrix_sync(b_lo, bp + 128 * 136, 136);
                    wmma::mma_sync(acc[n], a_hi, b_hi, acc[n]);
                    wmma::mma_sync(acc[n], a_hi, b_lo, acc[n]);
                    wmma::mma_sync(acc[n], a_lo, b_hi, acc[n]);
                }
            }
        }
        __syncthreads();   // all warps done READING A -> safe to overwrite as sOut

#pragma unroll
        for (int n = 0; n < 2; n++)
            wmma::store_matrix_sync(sOut + (m * 16) * 132 + np * 32 + n * 16,
                                    acc[n], 132, wmma::mem_row_major);
        __syncthreads();   // sOut complete

        // epilogue: this warp's 4 edges, all float4, warp-reduce
#pragma unroll
        for (int i = 0; i < 4; i++) {
            int sv = __shfl_sync(0xffffffffu, myi, i);
            int dv = __shfl_sync(0xffffffffu, myi, 4 + i);
            int e = 4 * w + i;
            float4 o = ((const float4*)(sOut + e * 132))[lane];
            float4 qd = ((const float4*)(g_Q + (size_t)dv * 256))[lane];
            float4 qs = ((const float4*)(g_Q + (size_t)sv * 256 + 128))[lane];
            float s = fmaxf(o.x + qd.x + qs.x + b1v.x, 0.f) * w2v.x
                    + fmaxf(o.y + qd.y + qs.y + b1v.y, 0.f) * w2v.y
                    + fmaxf(o.z + qd.z + qs.z + b1v.z, 0.f) * w2v.z
                    + fmaxf(o.w + qd.w + qs.w + b1v.w, 0.f) * w2v.w;
#pragma unroll
            for (int off = 16; off > 0; off >>= 1)
                s += __shfl_down_sync(0xffffffffu, s, off);
            if (lane == 0 && eb + e < E) out[eb + e] = s + bias2;
        }
        __syncthreads();   // sOut (== A region) free for next gather
    }
}

// ---------------------------------------------------------------------------
extern "C" void kernel_launch(void* const* d_in, const int* in_sizes, int n_in,
                              void* d_out, int out_size) {
    const float *nf = 0, *centroid = 0, *W1 = 0, *b1 = 0, *W2 = 0, *b2 = 0;
    const void* ei = 0;
    int nf_elems = 0, cen_elems = 0;
    int last_size1 = -1;

    for (int i = 0; i < n_in; i++) {
        int s = in_sizes[i];
        if (s == 1) { last_size1 = i; continue; }
        if (s == 128) {
            if (!b1) b1 = (const float*)d_in[i];
            else     W2 = (const float*)d_in[i];
            continue;
        }
        if (s == 2048) { centroid = (const float*)d_in[i]; cen_elems = s; continue; }
        if (s == 49152) { W1 = (const float*)d_in[i]; continue; }
        if (s == 2 * out_size) { ei = d_in[i]; continue; }
        if (s > nf_elems) { nf = (const float*)d_in[i]; nf_elems = s; }
    }
    if (last_size1 >= 0) b2 = (const float*)d_in[last_size1];

    const int E = out_size;
    const int n_nodes = nf_elems / DIM;
    const int bs = cen_elems / DIM;
    const int npg = n_nodes / (bs > 0 ? bs : 1);

    cudaFuncSetAttribute(precompute_kernel,
                         cudaFuncAttributeMaxDynamicSharedMemorySize, PRE_SMEM);
    precompute_kernel<<<((n_nodes + 63) / 64) * 2, 512, PRE_SMEM>>>(nf, centroid, W1,
                                                                    n_nodes, npg);

    detect_idx_kernel<<<1, 256>>>((const unsigned int*)ei);

    int sms = 148;
    cudaDeviceGetAttribute(&sms, cudaDevAttrMultiProcessorCount, 0);

    cudaFuncSetAttribute(edge_kernel,
                         cudaFuncAttributeMaxDynamicSharedMemorySize, EDGE_SMEM);
    edge_kernel<<<sms * 2, 512, EDGE_SMEM>>>(nf, ei, W1, b1, W2, b2, (float*)d_out, E);
}

// round 10
// speedup vs baseline: 2.6143x; 1.7355x over previous
#include <cuda_runtime.h>
#include <cuda_fp16.h>
#include <mma.h>
using namespace nvcuda;

#define DIM 128
#define MAX_NODES 65536

__device__ float g_Q[MAX_NODES * 256];
__device__ int g_idx64;

// ---------------------------------------------------------------------------
__global__ void detect_idx_kernel(const unsigned int* __restrict__ w) {
    __shared__ int s_any;
    if (threadIdx.x == 0) s_any = 0;
    __syncthreads();
    int found = 0;
    for (int i = threadIdx.x; i < 4096; i += blockDim.x)
        if (w[2 * i + 1] != 0u) found = 1;
    if (found) atomicOr(&s_any, 1);
    __syncthreads();
    if (threadIdx.x == 0) g_idx64 = (s_any == 0) ? 1 : 0;
}

// ---------------------------------------------------------------------------
// fp16 split of a float pair: v = hi + lo, |lo| <= 2^-12 |v| (A exact to 2^-23)
__device__ __forceinline__ void splitH(float v0, float v1, unsigned& h, unsigned& l) {
    __half2 hh = __floats2half2_rn(v0, v1);
    float2 hf = __half22float2(hh);
    __half2 ll = __floats2half2_rn(v0 - hf.x, v1 - hf.y);
    h = *(unsigned*)&hh;
    l = *(unsigned*)&ll;
}

typedef wmma::fragment<wmma::matrix_a, 16, 16, 16, __half, wmma::row_major> FragA;
typedef wmma::fragment<wmma::matrix_b, 16, 16, 16, __half, wmma::row_major> FragB;
typedef wmma::fragment<wmma::accumulator, 16, 16, 16, float> FragC;

// ---------------------------------------------------------------------------
// Precompute: CTA = (128-node tile, n-half). Q[node][half*128+c] =
// residual @ W1{b,c}. W fp16 (no split) 34.8KB + A hi/lo 69.6KB -> 2 CTA/SM.
// Warp = (m-pair = w>>2, np = w&3): 2m x 2n tiles, B loaded once per k.
// ---------------------------------------------------------------------------
#define PRE_SMEM (128 * 136 * 2 + 2 * 128 * 136 * 2)

__global__ __launch_bounds__(512, 2)
void precompute_kernel(const float* __restrict__ nf, const float* __restrict__ centroid,
                       const float* __restrict__ W1, int n_nodes, int npg) {
    extern __shared__ char sm[];
    __half* sW   = (__half*)sm;              // [128 k][136 n]  (fp16, no split)
    __half* sA_hi = sW + 128 * 136;          // [128 node][136 k]
    __half* sA_lo = sA_hi + 128 * 136;

    const int t = threadIdx.x;
    const int half = blockIdx.x & 1;
    const int base = (blockIdx.x >> 1) * 128;

    const float* Wsrc = W1 + (1 + half) * DIM * DIM;   // W1b or W1c, [k][n]
    for (int i = t; i < 128 * 128; i += 512) {
        int k = i >> 7, n = i & 127;
        sW[k * 136 + n] = __float2half_rn(Wsrc[i]);
    }
    __syncthreads();

    if (base + 128 > n_nodes) {   // scalar fallback for partial tile
        for (int node = base; node < n_nodes; node++) {
            const float* row = nf + (size_t)node * DIM;
            const float* cen = centroid + (size_t)(node / npg) * DIM;
            for (int c = t; c < 128; c += 512) {
                const float* wc = Wsrc + c;
                float acc = 0.f;
                for (int k = 0; k < DIM; k++) acc += (row[k] - cen[k]) * wc[k * DIM];
                g_Q[(size_t)node * 256 + half * 128 + c] = acc;
            }
        }
        return;
    }

    // residuals: coalesced float4 loads, fp16 hi/lo split
    for (int i = t; i < 128 * 32; i += 512) {
        int node = i >> 5, c4 = i & 31;
        float4 v = ((const float4*)nf)[(size_t)(base + node) * 32 + c4];
        float4 c = ((const float4*)centroid)[(size_t)((base + node) / npg) * 32 + c4];
        unsigned h0, l0, h1, l1;
        splitH(v.x - c.x, v.y - c.y, h0, l0);
        splitH(v.z - c.z, v.w - c.w, h1, l1);
        ((uint2*)(sA_hi + node * 136))[c4] = make_uint2(h0, h1);
        ((uint2*)(sA_lo + node * 136))[c4] = make_uint2(l0, l1);
    }
    __syncthreads();

    const int w = t >> 5;
    const int np = w & 3;       // 32-col group
    const int mp = w >> 2;      // m-pair: rows 32*mp .. 32*mp+31
    const __half* Ah = sA_hi + (mp * 32) * 136;
    const __half* Al = sA_lo + (mp * 32) * 136;

    FragC acc[2][2];
#pragma unroll
    for (int mi = 0; mi < 2; mi++)
#pragma unroll
        for (int n = 0; n < 2; n++) wmma::fill_fragment(acc[mi][n], 0.f);

#pragma unroll
    for (int k = 0; k < 8; k++) {
        FragB b0, b1;
        const __half* bp = sW + (k * 16) * 136 + np * 32;
        wmma::load_matrix_sync(b0, bp, 136);
        wmma::load_matrix_sync(b1, bp + 16, 136);
#pragma unroll
        for (int mi = 0; mi < 2; mi++) {
            FragA a_hi, a_lo;
            wmma::load_matrix_sync(a_hi, Ah + (mi * 16) * 136 + k * 16, 136);
            wmma::load_matrix_sync(a_lo, Al + (mi * 16) * 136 + k * 16, 136);
            wmma::mma_sync(acc[mi][0], a_hi, b0, acc[mi][0]);
            wmma::mma_sync(acc[mi][0], a_lo, b0, acc[mi][0]);
            wmma::mma_sync(acc[mi][1], a_hi, b1, acc[mi][1]);
            wmma::mma_sync(acc[mi][1], a_lo, b1, acc[mi][1]);
        }
    }
#pragma unroll
    for (int mi = 0; mi < 2; mi++)
#pragma unroll
        for (int n = 0; n < 2; n++)
            wmma::store_matrix_sync(
                g_Q + (size_t)(base + mp * 32 + mi * 16) * 256
                    + half * 128 + np * 32 + n * 16,
                acc[mi][n], 256, wmma::mem_row_major);
}

// ---------------------------------------------------------------------------
// Edge kernel: 512 thr / 16 warps, 128-edge tiles, sOut aliased onto A.
// W fp16 (no split) 34.8KB; union(A 69.6KB, sOut 67.6KB); ~104KB -> 2 CTA/SM.
//   gather: warp w owns edges 8w..8w+7 (float4 rows, fp16 hi/lo split)
//   MMA: warp = (m-pair = w>>2, np = w&3); 2 passes: Ah*W + Al*W
//   epilogue: warp w epilogues its 8 edges
// ---------------------------------------------------------------------------
#define EDGE_SMEM (128 * 136 * 2 + 2 * 128 * 136 * 2 + 2048)

__global__ __launch_bounds__(512, 2)
void edge_kernel(const float* __restrict__ nf, const void* __restrict__ ei,
                 const float* __restrict__ W1, const float* __restrict__ b1,
                 const float* __restrict__ W2, const float* __restrict__ b2,
                 float* __restrict__ out, int E) {
    extern __shared__ char sm[];
    __half* sW = (__half*)sm;                    // [128 k][136 n]
    char* sU = (char*)(sW + 128 * 136);          // union region
    __half* sA_hi = (__half*)sU;                 // [128 e][136 k]
    __half* sA_lo = sA_hi + 128 * 136;
    float* sOut = (float*)sU;                    // [128 e][132 n] (alias)
    float* sB1 = (float*)(sU + 2 * 128 * 136 * 2);   // 128
    float* sW2 = sB1 + 128;                          // 128
    int* sSrc = (int*)(sW2 + 128);                   // 128
    int* sDst = sSrc + 128;                          // 128

    const int t = threadIdx.x;
    for (int i = t; i < DIM * DIM; i += 512) {
        int k = i >> 7, n = i & 127;
        sW[k * 136 + n] = __float2half_rn(W1[i]);   // W1a block [k][n]
    }
    if (t < DIM) { sB1[t] = b1[t]; sW2[t] = W2[t]; }
    __syncthreads();

    const int w = t >> 5;
    const int lane = t & 31;
    const int np = w & 3;       // 32-col group
    const int mp = w >> 2;      // m-pair

    const float4 b1v = ((const float4*)sB1)[lane];
    const float4 w2v = ((const float4*)sW2)[lane];
    const float bias2 = b2[0];

    const int mode64 = g_idx64;
    const long long* ei64 = (const long long*)ei;
    const int* ei32 = (const int*)ei;

    const int tiles = (E + 127) >> 7;
    for (int tile = blockIdx.x; tile < tiles; tile += gridDim.x) {
        const int eb = tile * 128;

        // phase 1: indices -> smem
        if (t < 256) {
            int e = t & 127;
            int eid = eb + e;
            int v = 0;
            if (eid < E) {
                if (t < 128) v = mode64 ? (int)ei64[eid] : ei32[eid];
                else         v = mode64 ? (int)ei64[E + eid] : ei32[E + eid];
            }
            if (t < 128) sSrc[e] = v; else sDst[e] = v;
        }
        __syncthreads();

        // phase 2: gather 8 edges/warp; lane covers cols 4*lane..4*lane+3
#pragma unroll
        for (int i = 0; i < 8; i++) {
            int e = 8 * w + i;
            int sv = sSrc[e], dv = sDst[e];
            float4 a = ((const float4*)(nf + (size_t)dv * DIM))[lane];
            float4 b = ((const float4*)(nf + (size_t)sv * DIM))[lane];
            unsigned h0, l0, h1, l1;
            splitH(fabsf(a.x - b.x), fabsf(a.y - b.y), h0, l0);
            splitH(fabsf(a.z - b.z), fabsf(a.w - b.w), h1, l1);
            ((uint2*)(sA_hi + e * 136))[lane] = make_uint2(h0, h1);
            ((uint2*)(sA_lo + e * 136))[lane] = make_uint2(l0, l1);
        }
        __syncthreads();

        // phase 3: MMA into register fragments (2 m-tiles x 2 n-tiles)
        FragC acc[2][2];
#pragma unroll
        for (int mi = 0; mi < 2; mi++)
#pragma unroll
            for (int n = 0; n < 2; n++) wmma::fill_fragment(acc[mi][n], 0.f);
        {
            const __half* Ah = sA_hi + (mp * 32) * 136;
            const __half* Al = sA_lo + (mp * 32) * 136;
#pragma unroll
            for (int k = 0; k < 8; k++) {
                FragB b0, b1;
                const __half* bp = sW + (k * 16) * 136 + np * 32;
                wmma::load_matrix_sync(b0, bp, 136);
                wmma::load_matrix_sync(b1, bp + 16, 136);
#pragma unroll
                for (int mi = 0; mi < 2; mi++) {
                    FragA a_hi, a_lo;
                    wmma::load_matrix_sync(a_hi, Ah + (mi * 16) * 136 + k * 16, 136);
                    wmma::load_matrix_sync(a_lo, Al + (mi * 16) * 136 + k * 16, 136);
                    wmma::mma_sync(acc[mi][0], a_hi, b0, acc[mi][0]);
                    wmma::mma_sync(acc[mi][0], a_lo, b0, acc[mi][0]);
                    wmma::mma_sync(acc[mi][1], a_hi, b1, acc[mi][1]);
                    wmma::mma_sync(acc[mi][1], a_lo, b1, acc[mi][1]);
                }
            }
        }
        __syncthreads();   // all warps done READING A -> safe to alias as sOut

#pragma unroll
        for (int mi = 0; mi < 2; mi++)
#pragma unroll
            for (int n = 0; n < 2; n++)
                wmma::store_matrix_sync(
                    sOut + (mp * 32 + mi * 16) * 132 + np * 32 + n * 16,
                    acc[mi][n], 132, wmma::mem_row_major);
        __syncthreads();   // sOut complete

        // phase 4: epilogue — 8 edges/warp, float4, warp-reduce
#pragma unroll
        for (int i = 0; i < 8; i++) {
            int e = 8 * w + i;
            int eid = eb + e;
            int sv = sSrc[e], dv = sDst[e];
            float4 o = ((const float4*)(sOut + e * 132))[lane];
            float4 qd = ((const float4*)(g_Q + (size_t)dv * 256))[lane];
            float4 qs = ((const float4*)(g_Q + (size_t)sv * 256 + 128))[lane];
            float s = fmaxf(o.x + qd.x + qs.x + b1v.x, 0.f) * w2v.x
                    + fmaxf(o.y + qd.y + qs.y + b1v.y, 0.f) * w2v.y
                    + fmaxf(o.z + qd.z + qs.z + b1v.z, 0.f) * w2v.z
                    + fmaxf(o.w + qd.w + qs.w + b1v.w, 0.f) * w2v.w;
#pragma unroll
            for (int off = 16; off > 0; off >>= 1)
                s += __shfl_down_sync(0xffffffffu, s, off);
            if (lane == 0 && eid < E) out[eid] = s + bias2;
        }
        __syncthreads();   // sOut (== A region) free for next gather
    }
}

// ---------------------------------------------------------------------------
extern "C" void kernel_launch(void* const* d_in, const int* in_sizes, int n_in,
                              void* d_out, int out_size) {
    const float *nf = 0, *centroid = 0, *W1 = 0, *b1 = 0, *W2 = 0, *b2 = 0;
    const void* ei = 0;
    int nf_elems = 0, cen_elems = 0;
    int last_size1 = -1;

    for (int i = 0; i < n_in; i++) {
        int s = in_sizes[i];
        if (s == 1) { last_size1 = i; continue; }
        if (s == 128) {
            if (!b1) b1 = (const float*)d_in[i];
            else     W2 = (const float*)d_in[i];
            continue;
        }
        if (s == 2048) { centroid = (const float*)d_in[i]; cen_elems = s; continue; }
        if (s == 49152) { W1 = (const float*)d_in[i]; continue; }
        if (s == 2 * out_size) { ei = d_in[i]; continue; }
        if (s > nf_elems) { nf = (const float*)d_in[i]; nf_elems = s; }
    }
    if (last_size1 >= 0) b2 = (const float*)d_in[last_size1];

    const int E = out_size;
    const int n_nodes = nf_elems / DIM;
    const int bs = cen_elems / DIM;
    const int npg = n_nodes / (bs > 0 ? bs : 1);

    cudaFuncSetAttribute(precompute_kernel,
                         cudaFuncAttributeMaxDynamicSharedMemorySize, PRE_SMEM);
    precompute_kernel<<<((n_nodes + 127) / 128) * 2, 512, PRE_SMEM>>>(nf, centroid, W1,
                                                                      n_nodes, npg);

    detect_idx_kernel<<<1, 256>>>((const unsigned int*)ei);

    int sms = 148;
    cudaDeviceGetAttribute(&sms, cudaDevAttrMultiProcessorCount, 0);

    cudaFuncSetAttribute(edge_kernel,
                         cudaFuncAttributeMaxDynamicSharedMemorySize, EDGE_SMEM);
    edge_kernel<<<sms * 2, 512, EDGE_SMEM>>>(nf, ei, W1, b1, W2, b2, (float*)d_out, E);
}

// round 11
// speedup vs baseline: 3.6239x; 1.3862x over previous
#include <cuda_runtime.h>
#include <cuda_fp16.h>
#include <mma.h>
using namespace nvcuda;

#define DIM 128
#define MAX_NODES 65536

__device__ __half g_Qh[MAX_NODES * 256];
__device__ int g_idx64;

typedef wmma::fragment<wmma::matrix_a, 16, 16, 16, __half, wmma::row_major> FragA;
typedef wmma::fragment<wmma::matrix_b, 16, 16, 16, __half, wmma::row_major> FragB;
typedef wmma::fragment<wmma::accumulator, 16, 16, 16, float> FragC;

// fp16 split (used in precompute A only): v = hi + lo
__device__ __forceinline__ void splitH(float v0, float v1, unsigned& h, unsigned& l) {
    __half2 hh = __floats2half2_rn(v0, v1);
    float2 hf = __half22float2(hh);
    __half2 ll = __floats2half2_rn(v0 - hf.x, v1 - hf.y);
    h = *(unsigned*)&hh;
    l = *(unsigned*)&ll;
}

// ---------------------------------------------------------------------------
// Precompute: CTA = (128-node tile, n-half). Q[node][half*128+c] =
// residual @ W1{b,c}, fp16 A-split (2-pass) for accuracy, result stored fp16.
// smem: W 34.8K + union(A hi/lo 69.6K, staging 67.6K) = 104.4K -> 2 CTA/SM.
// Block 0 additionally performs the edge-index dtype scan (fused detect).
// ---------------------------------------------------------------------------
#define PRE_SMEM (128 * 136 * 2 + 2 * 128 * 136 * 2)

__global__ __launch_bounds__(512, 2)
void precompute_kernel(const float* __restrict__ nf, const float* __restrict__ centroid,
                       const float* __restrict__ W1, const unsigned* __restrict__ eiw,
                       int n_nodes, int npg) {
    extern __shared__ char sm[];
    __half* sW    = (__half*)sm;             // [128 k][136 n] fp16
    char* sU      = sm + 128 * 136 * 2;      // union region
    __half* sA_hi = (__half*)sU;             // [128 node][136 k]
    __half* sA_lo = sA_hi + 128 * 136;
    float* sStage = (float*)sU;              // [128 node][132 c] (alias, post-MMA)

    const int t = threadIdx.x;
    const int half = blockIdx.x & 1;
    const int base = (blockIdx.x >> 1) * 128;

    // fused detect (block 0): int64 ids have all-zero odd words
    if (blockIdx.x == 0) {
        __shared__ int s_any;
        if (t == 0) s_any = 0;
        __syncthreads();
        int found = 0;
        for (int i = t; i < 4096; i += 512)
            if (eiw[2 * i + 1] != 0u) found = 1;
        if (found) atomicOr(&s_any, 1);
        __syncthreads();
        if (t == 0) g_idx64 = (s_any == 0) ? 1 : 0;
    }

    const float* Wsrc = W1 + (1 + half) * DIM * DIM;   // W1b or W1c, [k][n]
    for (int i = t; i < 128 * 128; i += 512) {
        int k = i >> 7, n = i & 127;
        sW[k * 136 + n] = __float2half_rn(Wsrc[i]);
    }
    __syncthreads();

    if (base + 128 > n_nodes) {   // scalar fallback for partial tile
        for (int node = base; node < n_nodes; node++) {
            const float* row = nf + (size_t)node * DIM;
            const float* cen = centroid + (size_t)(node / npg) * DIM;
            for (int c = t; c < 128; c += 512) {
                const float* wc = Wsrc + c;
                float acc = 0.f;
                for (int k = 0; k < DIM; k++) acc += (row[k] - cen[k]) * wc[k * DIM];
                g_Qh[(size_t)node * 256 + half * 128 + c] = __float2half_rn(acc);
            }
        }
        return;
    }

    // residuals -> fp16 hi/lo
    for (int i = t; i < 128 * 32; i += 512) {
        int node = i >> 5, c4 = i & 31;
        float4 v = ((const float4*)nf)[(size_t)(base + node) * 32 + c4];
        float4 c = ((const float4*)centroid)[(size_t)((base + node) / npg) * 32 + c4];
        unsigned h0, l0, h1, l1;
        splitH(v.x - c.x, v.y - c.y, h0, l0);
        splitH(v.z - c.z, v.w - c.w, h1, l1);
        ((uint2*)(sA_hi + node * 136))[c4] = make_uint2(h0, h1);
        ((uint2*)(sA_lo + node * 136))[c4] = make_uint2(l0, l1);
    }
    __syncthreads();

    const int w = t >> 5;
    const int np = w & 3;
    const int mp = w >> 2;
    {
        const __half* Ah = sA_hi + (mp * 32) * 136;
        const __half* Al = sA_lo + (mp * 32) * 136;

        FragC acc[2][2];
#pragma unroll
        for (int mi = 0; mi < 2; mi++)
#pragma unroll
            for (int n = 0; n < 2; n++) wmma::fill_fragment(acc[mi][n], 0.f);

#pragma unroll
        for (int k = 0; k < 8; k++) {
            FragB b0, b1;
            const __half* bp = sW + (k * 16) * 136 + np * 32;
            wmma::load_matrix_sync(b0, bp, 136);
            wmma::load_matrix_sync(b1, bp + 16, 136);
#pragma unroll
            for (int mi = 0; mi < 2; mi++) {
                FragA a_hi, a_lo;
                wmma::load_matrix_sync(a_hi, Ah + (mi * 16) * 136 + k * 16, 136);
                wmma::load_matrix_sync(a_lo, Al + (mi * 16) * 136 + k * 16, 136);
                wmma::mma_sync(acc[mi][0], a_hi, b0, acc[mi][0]);
                wmma::mma_sync(acc[mi][0], a_lo, b0, acc[mi][0]);
                wmma::mma_sync(acc[mi][1], a_hi, b1, acc[mi][1]);
                wmma::mma_sync(acc[mi][1], a_lo, b1, acc[mi][1]);
            }
        }
        __syncthreads();   // all warps done reading A -> alias as staging

#pragma unroll
        for (int mi = 0; mi < 2; mi++)
#pragma unroll
            for (int n = 0; n < 2; n++)
                wmma::store_matrix_sync(
                    sStage + (mp * 32 + mi * 16) * 132 + np * 32 + n * 16,
                    acc[mi][n], 132, wmma::mem_row_major);
    }
    __syncthreads();

    // convert staging -> fp16 Q, coalesced half2 stores
    for (int i = t; i < 128 * 64; i += 512) {
        int node = i >> 6, cp = i & 63;
        float v0 = sStage[node * 132 + 2 * cp];
        float v1 = sStage[node * 132 + 2 * cp + 1];
        __half2 hv = __floats2half2_rn(v0, v1);
        *(__half2*)(g_Qh + (size_t)(base + node) * 256 + half * 128 + 2 * cp) = hv;
    }
}

// ---------------------------------------------------------------------------
// Edge kernel: 512 thr / 16 warps, 128-edge tiles. SINGLE-pass fp16 A
// (error budget: W fp16 + A fp16 + Q fp16 ~ 3.5e-4 << 1e-3).
// smem: W 34.8K + union(A 34.8K, sOut 67.6K) + misc = ~104K -> 2 CTA/SM.
// ---------------------------------------------------------------------------
#define EDGE_SMEM (128 * 136 * 2 + 128 * 132 * 4 + 2048)

__global__ __launch_bounds__(512, 2)
void edge_kernel(const float* __restrict__ nf, const void* __restrict__ ei,
                 const float* __restrict__ W1, const float* __restrict__ b1,
                 const float* __restrict__ W2, const float* __restrict__ b2,
                 float* __restrict__ out, int E) {
    extern __shared__ char sm[];
    __half* sW = (__half*)sm;                    // [128 k][136 n]
    char* sU = sm + 128 * 136 * 2;               // union region
    __half* sA = (__half*)sU;                    // [128 e][136 k]
    float* sOut = (float*)sU;                    // [128 e][132 n] (alias)
    float* sB1 = (float*)(sU + 128 * 132 * 4);   // 128
    float* sW2 = sB1 + 128;                      // 128
    int* sSrc = (int*)(sW2 + 128);               // 128
    int* sDst = sSrc + 128;                      // 128

    const int t = threadIdx.x;
    for (int i = t; i < DIM * DIM; i += 512) {
        int k = i >> 7, n = i & 127;
        sW[k * 136 + n] = __float2half_rn(W1[i]);   // W1a block [k][n]
    }
    if (t < DIM) { sB1[t] = b1[t]; sW2[t] = W2[t]; }
    __syncthreads();

    const int w = t >> 5;
    const int lane = t & 31;
    const int np = w & 3;
    const int mp = w >> 2;

    const float4 b1v = ((const float4*)sB1)[lane];
    const float4 w2v = ((const float4*)sW2)[lane];
    const float bias2 = b2[0];

    const int mode64 = g_idx64;
    const long long* ei64 = (const long long*)ei;
    const int* ei32 = (const int*)ei;

    const int tiles = (E + 127) >> 7;
    for (int tile = blockIdx.x; tile < tiles; tile += gridDim.x) {
        const int eb = tile * 128;

        // phase 1: indices
        if (t < 256) {
            int e = t & 127;
            int eid = eb + e;
            int v = 0;
            if (eid < E) {
                if (t < 128) v = mode64 ? (int)ei64[eid] : ei32[eid];
                else         v = mode64 ? (int)ei64[E + eid] : ei32[E + eid];
            }
            if (t < 128) sSrc[e] = v; else sDst[e] = v;
        }
        __syncthreads();

        // phase 2: gather 8 edges/warp, |diff| -> fp16 (single precision level)
#pragma unroll
        for (int i = 0; i < 8; i++) {
            int e = 8 * w + i;
            int sv = sSrc[e], dv = sDst[e];
            float4 a = ((const float4*)(nf + (size_t)dv * DIM))[lane];
            float4 b = ((const float4*)(nf + (size_t)sv * DIM))[lane];
            __half2 p0 = __floats2half2_rn(fabsf(a.x - b.x), fabsf(a.y - b.y));
            __half2 p1 = __floats2half2_rn(fabsf(a.z - b.z), fabsf(a.w - b.w));
            ((uint2*)(sA + e * 136))[lane] =
                make_uint2(*(unsigned*)&p0, *(unsigned*)&p1);
        }
        __syncthreads();

        // phase 3: MMA (single pass), 2m x 2n per warp
        FragC acc[2][2];
#pragma unroll
        for (int mi = 0; mi < 2; mi++)
#pragma unroll
            for (int n = 0; n < 2; n++) wmma::fill_fragment(acc[mi][n], 0.f);
        {
            const __half* Ah = sA + (mp * 32) * 136;
#pragma unroll
            for (int k = 0; k < 8; k++) {
                FragB b0, b1;
                const __half* bp = sW + (k * 16) * 136 + np * 32;
                wmma::load_matrix_sync(b0, bp, 136);
                wmma::load_matrix_sync(b1, bp + 16, 136);
#pragma unroll
                for (int mi = 0; mi < 2; mi++) {
                    FragA af;
                    wmma::load_matrix_sync(af, Ah + (mi * 16) * 136 + k * 16, 136);
                    wmma::mma_sync(acc[mi][0], af, b0, acc[mi][0]);
                    wmma::mma_sync(acc[mi][1], af, b1, acc[mi][1]);
                }
            }
        }
        __syncthreads();   // done reading A -> alias as sOut

#pragma unroll
        for (int mi = 0; mi < 2; mi++)
#pragma unroll
            for (int n = 0; n < 2; n++)
                wmma::store_matrix_sync(
                    sOut + (mp * 32 + mi * 16) * 132 + np * 32 + n * 16,
                    acc[mi][n], 132, wmma::mem_row_major);
        __syncthreads();

        // phase 4: epilogue, Q gathered as fp16 (8 bytes/lane/side)
#pragma unroll
        for (int i = 0; i < 8; i++) {
            int e = 8 * w + i;
            int eid = eb + e;
            int sv = sSrc[e], dv = sDst[e];
            float4 o = ((const float4*)(sOut + e * 132))[lane];
            uint2 qdr = ((const uint2*)(g_Qh + (size_t)dv * 256))[lane];
            uint2 qsr = ((const uint2*)(g_Qh + (size_t)sv * 256 + 128))[lane];
            float2 qd0 = __half22float2(*(__half2*)&qdr.x);
            float2 qd1 = __half22float2(*(__half2*)&qdr.y);
            float2 qs0 = __half22float2(*(__half2*)&qsr.x);
            float2 qs1 = __half22float2(*(__half2*)&qsr.y);
            float s = fmaxf(o.x + qd0.x + qs0.x + b1v.x, 0.f) * w2v.x
                    + fmaxf(o.y + qd0.y + qs0.y + b1v.y, 0.f) * w2v.y
                    + fmaxf(o.z + qd1.x + qs1.x + b1v.z, 0.f) * w2v.z
                    + fmaxf(o.w + qd1.y + qs1.y + b1v.w, 0.f) * w2v.w;
#pragma unroll
            for (int off = 16; off > 0; off >>= 1)
                s += __shfl_down_sync(0xffffffffu, s, off);
            if (lane == 0 && eid < E) out[eid] = s + bias2;
        }
        __syncthreads();   // sOut (== A region) free for next gather
    }
}

// ---------------------------------------------------------------------------
extern "C" void kernel_launch(void* const* d_in, const int* in_sizes, int n_in,
                              void* d_out, int out_size) {
    const float *nf = 0, *centroid = 0, *W1 = 0, *b1 = 0, *W2 = 0, *b2 = 0;
    const void* ei = 0;
    int nf_elems = 0, cen_elems = 0;
    int last_size1 = -1;

    for (int i = 0; i < n_in; i++) {
        int s = in_sizes[i];
        if (s == 1) { last_size1 = i; continue; }
        if (s == 128) {
            if (!b1) b1 = (const float*)d_in[i];
            else     W2 = (const float*)d_in[i];
            continue;
        }
        if (s == 2048) { centroid = (const float*)d_in[i]; cen_elems = s; continue; }
        if (s == 49152) { W1 = (const float*)d_in[i]; continue; }
        if (s == 2 * out_size) { ei = d_in[i]; continue; }
        if (s > nf_elems) { nf = (const float*)d_in[i]; nf_elems = s; }
    }
    if (last_size1 >= 0) b2 = (const float*)d_in[last_size1];

    const int E = out_size;
    const int n_nodes = nf_elems / DIM;
    const int bs = cen_elems / DIM;
    const int npg = n_nodes / (bs > 0 ? bs : 1);

    cudaFuncSetAttribute(precompute_kernel,
                         cudaFuncAttributeMaxDynamicSharedMemorySize, PRE_SMEM);
    precompute_kernel<<<((n_nodes + 127) / 128) * 2, 512, PRE_SMEM>>>(
        nf, centroid, W1, (const unsigned*)ei, n_nodes, npg);

    int sms = 148;
    cudaDeviceGetAttribute(&sms, cudaDevAttrMultiProcessorCount, 0);

    cudaFuncSetAttribute(edge_kernel,
                         cudaFuncAttributeMaxDynamicSharedMemorySize, EDGE_SMEM);
    edge_kernel<<<sms * 2, 512, EDGE_SMEM>>>(nf, ei, W1, b1, W2, b2, (float*)d_out, E);
}

// round 12
// speedup vs baseline: 3.7992x; 1.0484x over previous
#include <cuda_runtime.h>
#include <cuda_fp16.h>
#include <mma.h>
using namespace nvcuda;

#define DIM 128
#define MAX_NODES 65536

__device__ __half g_Qh[MAX_NODES * 256];
__device__ __half g_nfh[MAX_NODES * DIM];
__device__ int g_idx64;

typedef wmma::fragment<wmma::matrix_a, 16, 16, 16, __half, wmma::row_major> FragA;
typedef wmma::fragment<wmma::matrix_b, 16, 16, 16, __half, wmma::row_major> FragB;
typedef wmma::fragment<wmma::accumulator, 16, 16, 16, float> FragC;

// fp16 split (used in precompute A only): v = hi + lo
__device__ __forceinline__ void splitH(float v0, float v1, unsigned& h, unsigned& l) {
    __half2 hh = __floats2half2_rn(v0, v1);
    float2 hf = __half22float2(hh);
    __half2 ll = __floats2half2_rn(v0 - hf.x, v1 - hf.y);
    h = *(unsigned*)&hh;
    l = *(unsigned*)&ll;
}

// ---------------------------------------------------------------------------
// Precompute: CTA = (128-node tile, n-half). Q[node][half*128+c] =
// residual @ W1{b,c}, fp16 A-split (2-pass), result stored fp16.
// half==0 CTAs additionally store nf as fp16 into g_nfh (free: rows already
// streamed for residuals). Block 0 performs the fused edge-index dtype scan.
// ---------------------------------------------------------------------------
#define PRE_SMEM (128 * 136 * 2 + 2 * 128 * 136 * 2)

__global__ __launch_bounds__(512, 2)
void precompute_kernel(const float* __restrict__ nf, const float* __restrict__ centroid,
                       const float* __restrict__ W1, const unsigned* __restrict__ eiw,
                       int n_nodes, int npg) {
    extern __shared__ char sm[];
    __half* sW    = (__half*)sm;             // [128 k][136 n] fp16
    char* sU      = sm + 128 * 136 * 2;      // union region
    __half* sA_hi = (__half*)sU;             // [128 node][136 k]
    __half* sA_lo = sA_hi + 128 * 136;
    float* sStage = (float*)sU;              // [128 node][132 c] (alias, post-MMA)

    const int t = threadIdx.x;
    const int half = blockIdx.x & 1;
    const int base = (blockIdx.x >> 1) * 128;

    // fused detect (block 0): int64 ids have all-zero odd words
    if (blockIdx.x == 0) {
        __shared__ int s_any;
        if (t == 0) s_any = 0;
        __syncthreads();
        int found = 0;
        for (int i = t; i < 4096; i += 512)
            if (eiw[2 * i + 1] != 0u) found = 1;
        if (found) atomicOr(&s_any, 1);
        __syncthreads();
        if (t == 0) g_idx64 = (s_any == 0) ? 1 : 0;
    }

    const float* Wsrc = W1 + (1 + half) * DIM * DIM;   // W1b or W1c, [k][n]
    for (int i = t; i < 128 * 128; i += 512) {
        int k = i >> 7, n = i & 127;
        sW[k * 136 + n] = __float2half_rn(Wsrc[i]);
    }
    __syncthreads();

    if (base + 128 > n_nodes) {   // scalar fallback for partial tile
        for (int node = base; node < n_nodes; node++) {
            const float* row = nf + (size_t)node * DIM;
            const float* cen = centroid + (size_t)(node / npg) * DIM;
            if (half == 0)
                for (int d = t; d < DIM; d += 512)
                    g_nfh[(size_t)node * DIM + d] = __float2half_rn(row[d]);
            for (int c = t; c < 128; c += 512) {
                const float* wc = Wsrc + c;
                float acc = 0.f;
                for (int k = 0; k < DIM; k++) acc += (row[k] - cen[k]) * wc[k * DIM];
                g_Qh[(size_t)node * 256 + half * 128 + c] = __float2half_rn(acc);
            }
        }
        return;
    }

    // residuals -> fp16 hi/lo; half==0 also stores fp16 nf copy
    for (int i = t; i < 128 * 32; i += 512) {
        int node = i >> 5, c4 = i & 31;
        float4 v = ((const float4*)nf)[(size_t)(base + node) * 32 + c4];
        float4 c = ((const float4*)centroid)[(size_t)((base + node) / npg) * 32 + c4];
        if (half == 0) {
            __half2 n0 = __floats2half2_rn(v.x, v.y);
            __half2 n1 = __floats2half2_rn(v.z, v.w);
            ((uint2*)(g_nfh + (size_t)(base + node) * DIM))[c4] =
                make_uint2(*(unsigned*)&n0, *(unsigned*)&n1);
        }
        unsigned h0, l0, h1, l1;
        splitH(v.x - c.x, v.y - c.y, h0, l0);
        splitH(v.z - c.z, v.w - c.w, h1, l1);
        ((uint2*)(sA_hi + node * 136))[c4] = make_uint2(h0, h1);
        ((uint2*)(sA_lo + node * 136))[c4] = make_uint2(l0, l1);
    }
    __syncthreads();

    const int w = t >> 5;
    const int np = w & 3;
    const int mp = w >> 2;
    {
        const __half* Ah = sA_hi + (mp * 32) * 136;
        const __half* Al = sA_lo + (mp * 32) * 136;

        FragC acc[2][2];
#pragma unroll
        for (int mi = 0; mi < 2; mi++)
#pragma unroll
            for (int n = 0; n < 2; n++) wmma::fill_fragment(acc[mi][n], 0.f);

#pragma unroll
        for (int k = 0; k < 8; k++) {
            FragB b0, b1;
            const __half* bp = sW + (k * 16) * 136 + np * 32;
            wmma::load_matrix_sync(b0, bp, 136);
            wmma::load_matrix_sync(b1, bp + 16, 136);
#pragma unroll
            for (int mi = 0; mi < 2; mi++) {
                FragA a_hi, a_lo;
                wmma::load_matrix_sync(a_hi, Ah + (mi * 16) * 136 + k * 16, 136);
                wmma::load_matrix_sync(a_lo, Al + (mi * 16) * 136 + k * 16, 136);
                wmma::mma_sync(acc[mi][0], a_hi, b0, acc[mi][0]);
                wmma::mma_sync(acc[mi][0], a_lo, b0, acc[mi][0]);
                wmma::mma_sync(acc[mi][1], a_hi, b1, acc[mi][1]);
                wmma::mma_sync(acc[mi][1], a_lo, b1, acc[mi][1]);
            }
        }
        __syncthreads();   // all warps done reading A -> alias as staging

#pragma unroll
        for (int mi = 0; mi < 2; mi++)
#pragma unroll
            for (int n = 0; n < 2; n++)
                wmma::store_matrix_sync(
                    sStage + (mp * 32 + mi * 16) * 132 + np * 32 + n * 16,
                    acc[mi][n], 132, wmma::mem_row_major);
    }
    __syncthreads();

    // convert staging -> fp16 Q, coalesced half2 stores
    for (int i = t; i < 128 * 64; i += 512) {
        int node = i >> 6, cp = i & 63;
        float v0 = sStage[node * 132 + 2 * cp];
        float v1 = sStage[node * 132 + 2 * cp + 1];
        __half2 hv = __floats2half2_rn(v0, v1);
        *(__half2*)(g_Qh + (size_t)(base + node) * 256 + half * 128 + 2 * cp) = hv;
    }
}

// ---------------------------------------------------------------------------
// Edge kernel: 512 thr / 16 warps, 128-edge tiles, single-pass fp16 A.
// Gather now reads fp16 nf (256B/row, half2 math) -> dominant L1 stream halved.
// smem: W 34.8K + union(A 34.8K, sOut 67.6K) + misc -> 2 CTA/SM.
// ---------------------------------------------------------------------------
#define EDGE_SMEM (128 * 136 * 2 + 128 * 132 * 4 + 2048)

__global__ __launch_bounds__(512, 2)
void edge_kernel(const void* __restrict__ ei,
                 const float* __restrict__ W1, const float* __restrict__ b1,
                 const float* __restrict__ W2, const float* __restrict__ b2,
                 float* __restrict__ out, int E) {
    extern __shared__ char sm[];
    __half* sW = (__half*)sm;                    // [128 k][136 n]
    char* sU = sm + 128 * 136 * 2;               // union region
    __half* sA = (__half*)sU;                    // [128 e][136 k]
    float* sOut = (float*)sU;                    // [128 e][132 n] (alias)
    float* sB1 = (float*)(sU + 128 * 132 * 4);   // 128
    float* sW2 = sB1 + 128;                      // 128
    int* sSrc = (int*)(sW2 + 128);               // 128
    int* sDst = sSrc + 128;                      // 128

    const int t = threadIdx.x;
    for (int i = t; i < DIM * DIM; i += 512) {
        int k = i >> 7, n = i & 127;
        sW[k * 136 + n] = __float2half_rn(W1[i]);   // W1a block [k][n]
    }
    if (t < DIM) { sB1[t] = b1[t]; sW2[t] = W2[t]; }
    __syncthreads();

    const int w = t >> 5;
    const int lane = t & 31;
    const int np = w & 3;
    const int mp = w >> 2;

    const float4 b1v = ((const float4*)sB1)[lane];
    const float4 w2v = ((const float4*)sW2)[lane];
    const float bias2 = b2[0];

    const int mode64 = g_idx64;
    const long long* ei64 = (const long long*)ei;
    const int* ei32 = (const int*)ei;

    const int tiles = (E + 127) >> 7;
    for (int tile = blockIdx.x; tile < tiles; tile += gridDim.x) {
        const int eb = tile * 128;

        // phase 1: indices
        if (t < 256) {
            int e = t & 127;
            int eid = eb + e;
            int v = 0;
            if (eid < E) {
                if (t < 128) v = mode64 ? (int)ei64[eid] : ei32[eid];
                else         v = mode64 ? (int)ei64[E + eid] : ei32[E + eid];
            }
            if (t < 128) sSrc[e] = v; else sDst[e] = v;
        }
        __syncthreads();

        // phase 2: gather 8 edges/warp from fp16 nf, |diff| in half2
#pragma unroll
        for (int i = 0; i < 8; i++) {
            int e = 8 * w + i;
            int sv = sSrc[e], dv = sDst[e];
            uint2 av = ((const uint2*)(g_nfh + (size_t)dv * DIM))[lane];
            uint2 bv = ((const uint2*)(g_nfh + (size_t)sv * DIM))[lane];
            __half2 d0 = __habs2(__hsub2(*(__half2*)&av.x, *(__half2*)&bv.x));
            __half2 d1 = __habs2(__hsub2(*(__half2*)&av.y, *(__half2*)&bv.y));
            ((uint2*)(sA + e * 136))[lane] =
                make_uint2(*(unsigned*)&d0, *(unsigned*)&d1);
        }
        __syncthreads();

        // phase 3: MMA (single pass), 2m x 2n per warp
        FragC acc[2][2];
#pragma unroll
        for (int mi = 0; mi < 2; mi++)
#pragma unroll
            for (int n = 0; n < 2; n++) wmma::fill_fragment(acc[mi][n], 0.f);
        {
            const __half* Ah = sA + (mp * 32) * 136;
#pragma unroll
            for (int k = 0; k < 8; k++) {
                FragB b0, b1;
                const __half* bp = sW + (k * 16) * 136 + np * 32;
                wmma::load_matrix_sync(b0, bp, 136);
                wmma::load_matrix_sync(b1, bp + 16, 136);
#pragma unroll
                for (int mi = 0; mi < 2; mi++) {
                    FragA af;
                    wmma::load_matrix_sync(af, Ah + (mi * 16) * 136 + k * 16, 136);
                    wmma::mma_sync(acc[mi][0], af, b0, acc[mi][0]);
                    wmma::mma_sync(acc[mi][1], af, b1, acc[mi][1]);
                }
            }
        }
        __syncthreads();   // done reading A -> alias as sOut

#pragma unroll
        for (int mi = 0; mi < 2; mi++)
#pragma unroll
            for (int n = 0; n < 2; n++)
                wmma::store_matrix_sync(
                    sOut + (mp * 32 + mi * 16) * 132 + np * 32 + n * 16,
                    acc[mi][n], 132, wmma::mem_row_major);
        __syncthreads();

        // phase 4: epilogue, Q gathered as fp16
#pragma unroll
        for (int i = 0; i < 8; i++) {
            int e = 8 * w + i;
            int eid = eb + e;
            int sv = sSrc[e], dv = sDst[e];
            float4 o = ((const float4*)(sOut + e * 132))[lane];
            uint2 qdr = ((const uint2*)(g_Qh + (size_t)dv * 256))[lane];
            uint2 qsr = ((const uint2*)(g_Qh + (size_t)sv * 256 + 128))[lane];
            float2 qd0 = __half22float2(*(__half2*)&qdr.x);
            float2 qd1 = __half22float2(*(__half2*)&qdr.y);
            float2 qs0 = __half22float2(*(__half2*)&qsr.x);
            float2 qs1 = __half22float2(*(__half2*)&qsr.y);
            float s = fmaxf(o.x + qd0.x + qs0.x + b1v.x, 0.f) * w2v.x
                    + fmaxf(o.y + qd0.y + qs0.y + b1v.y, 0.f) * w2v.y
                    + fmaxf(o.z + qd1.x + qs1.x + b1v.z, 0.f) * w2v.z
                    + fmaxf(o.w + qd1.y + qs1.y + b1v.w, 0.f) * w2v.w;
#pragma unroll
            for (int off = 16; off > 0; off >>= 1)
                s += __shfl_down_sync(0xffffffffu, s, off);
            if (lane == 0 && eid < E) out[eid] = s + bias2;
        }
        __syncthreads();   // sOut (== A region) free for next gather
    }
}

// ---------------------------------------------------------------------------
extern "C" void kernel_launch(void* const* d_in, const int* in_sizes, int n_in,
                              void* d_out, int out_size) {
    const float *nf = 0, *centroid = 0, *W1 = 0, *b1 = 0, *W2 = 0, *b2 = 0;
    const void* ei = 0;
    int nf_elems = 0, cen_elems = 0;
    int last_size1 = -1;

    for (int i = 0; i < n_in; i++) {
        int s = in_sizes[i];
        if (s == 1) { last_size1 = i; continue; }
        if (s == 128) {
            if (!b1) b1 = (const float*)d_in[i];
            else     W2 = (const float*)d_in[i];
            continue;
        }
        if (s == 2048) { centroid = (const float*)d_in[i]; cen_elems = s; continue; }
        if (s == 49152) { W1 = (const float*)d_in[i]; continue; }
        if (s == 2 * out_size) { ei = d_in[i]; continue; }
        if (s > nf_elems) { nf = (const float*)d_in[i]; nf_elems = s; }
    }
    if (last_size1 >= 0) b2 = (const float*)d_in[last_size1];

    const int E = out_size;
    const int n_nodes = nf_elems / DIM;
    const int bs = cen_elems / DIM;
    const int npg = n_nodes / (bs > 0 ? bs : 1);

    cudaFuncSetAttribute(precompute_kernel,
                         cudaFuncAttributeMaxDynamicSharedMemorySize, PRE_SMEM);
    precompute_kernel<<<((n_nodes + 127) / 128) * 2, 512, PRE_SMEM>>>(
        nf, centroid, W1, (const unsigned*)ei, n_nodes, npg);

    int sms = 148;
    cudaDeviceGetAttribute(&sms, cudaDevAttrMultiProcessorCount, 0);

    cudaFuncSetAttribute(edge_kernel,
                         cudaFuncAttributeMaxDynamicSharedMemorySize, EDGE_SMEM);
    edge_kernel<<<sms * 2, 512, EDGE_SMEM>>>(ei, W1, b1, W2, b2, (float*)d_out, E);
}